// round 1
// baseline (speedup 1.0000x reference)
#include <cuda_runtime.h>
#include <math.h>

#define D_MODEL 1024
#define B_SZ 4
#define T_SZ 4096
#define NROWS (B_SZ * T_SZ)          /* 16384 */
#define CHUNK 256
#define NCHUNK (T_SZ / CHUNK)        /* 16 */
#define NUNITS (B_SZ * NCHUNK)       /* 64 */
#define LN_EPS 1e-5f
#define DEN_EPS 1e-6f

// ---------------- scratch (device globals; no allocations allowed) -----------
__device__ float g_xn[(size_t)NROWS * D_MODEL];                 // 64 MB
__device__ float g_qkvg[(size_t)NROWS * 4 * D_MODEL];           // 256 MB  q|k|v|gate
__device__ float g_P[(size_t)NUNITS * D_MODEL * D_MODEL];       // 256 MB  chunk K^T V -> excl prefix S
__device__ float g_Pk[NUNITS * D_MODEL];                        // chunk K colsums -> excl prefix
__device__ float g_attn[(size_t)NUNITS * CHUNK * CHUNK];        // 16.8 MB
__device__ float g_num[(size_t)NROWS * D_MODEL];                // 64 MB
__device__ float g_den[NROWS];

// ---------------- LayerNorm ---------------------------------------------------
__global__ void ln_kernel(const float* __restrict__ x,
                          const float* __restrict__ g,
                          const float* __restrict__ b,
                          float* __restrict__ xn) {
    int row = blockIdx.x;
    const float* xr = x + (size_t)row * D_MODEL;
    float* outr = xn + (size_t)row * D_MODEL;
    int tid = threadIdx.x;

    float vals[4];
    float s = 0.f, ss = 0.f;
#pragma unroll
    for (int i = 0; i < 4; i++) {
        float v = xr[tid + i * 256];
        vals[i] = v;
        s += v;
        ss += v * v;
    }
#pragma unroll
    for (int o = 16; o > 0; o >>= 1) {
        s  += __shfl_xor_sync(0xffffffffu, s, o);
        ss += __shfl_xor_sync(0xffffffffu, ss, o);
    }
    __shared__ float sbuf[8], ssbuf[8];
    int warp = tid >> 5, lane = tid & 31;
    if (lane == 0) { sbuf[warp] = s; ssbuf[warp] = ss; }
    __syncthreads();
    float ts = 0.f, tss = 0.f;
#pragma unroll
    for (int w = 0; w < 8; w++) { ts += sbuf[w]; tss += ssbuf[w]; }
    float mu = ts * (1.0f / D_MODEL);
    float var = tss * (1.0f / D_MODEL) - mu * mu;
    float inv = rsqrtf(var + LN_EPS);
#pragma unroll
    for (int i = 0; i < 4; i++) {
        int d = tid + i * 256;
        outr[d] = (vals[i] - mu) * inv * g[d] + b[d];
    }
}

// ---------------- generic 128x128x8 fp32 GEMM --------------------------------
// A_KM:  A stored [K,M] row-major (computes A^T @ B)
// B_NK:  B stored [N,K] row-major (computes A @ B^T)
// ACCUM: C += result ; BIAS: add bias[n] ; MASKROW: causal mask within unit +
//        rowsum atomically added into den[u*M + row]
template <bool A_KM, bool B_NK, bool ACCUM, bool BIAS, bool MASKROW>
__global__ __launch_bounds__(256)
void gemm_kernel(const float* __restrict__ A, int lda, long long sA,
                 const float* __restrict__ B, int ldb, long long sB,
                 float* __restrict__ Cp, int ldc, long long sC,
                 const float* __restrict__ bias,
                 float* __restrict__ den,
                 int M, int N, int K) {
    __shared__ float As[8][128];
    __shared__ float Bs[8][128];

    int u = blockIdx.z;
    A  += (long long)u * sA;
    B  += (long long)u * sB;
    Cp += (long long)u * sC;

    int m0 = blockIdx.y * 128;
    int n0 = blockIdx.x * 128;
    int tid = threadIdx.x;
    int tx = tid & 15;
    int ty = tid >> 4;

    float acc[8][8];
#pragma unroll
    for (int i = 0; i < 8; i++)
#pragma unroll
        for (int j = 0; j < 8; j++) acc[i][j] = 0.f;

    for (int k0 = 0; k0 < K; k0 += 8) {
        if (A_KM) {
            int kk = tid >> 5;
            int mm = (tid & 31) * 4;
            float4 v = *reinterpret_cast<const float4*>(
                &A[(long long)(k0 + kk) * lda + m0 + mm]);
            *reinterpret_cast<float4*>(&As[kk][mm]) = v;
        } else {
            int mm = tid >> 1;
            int kk = (tid & 1) * 4;
            float4 v = *reinterpret_cast<const float4*>(
                &A[(long long)(m0 + mm) * lda + k0 + kk]);
            As[kk + 0][mm] = v.x; As[kk + 1][mm] = v.y;
            As[kk + 2][mm] = v.z; As[kk + 3][mm] = v.w;
        }
        if (B_NK) {
            int nn = tid >> 1;
            int kk = (tid & 1) * 4;
            float4 v = *reinterpret_cast<const float4*>(
                &B[(long long)(n0 + nn) * ldb + k0 + kk]);
            Bs[kk + 0][nn] = v.x; Bs[kk + 1][nn] = v.y;
            Bs[kk + 2][nn] = v.z; Bs[kk + 3][nn] = v.w;
        } else {
            int kk = tid >> 5;
            int nn = (tid & 31) * 4;
            float4 v = *reinterpret_cast<const float4*>(
                &B[(long long)(k0 + kk) * ldb + n0 + nn]);
            *reinterpret_cast<float4*>(&Bs[kk][nn]) = v;
        }
        __syncthreads();

#pragma unroll
        for (int kk = 0; kk < 8; kk++) {
            float ar[8], br[8];
#pragma unroll
            for (int i = 0; i < 8; i++) ar[i] = As[kk][ty * 8 + i];
#pragma unroll
            for (int j = 0; j < 8; j++) br[j] = Bs[kk][tx * 8 + j];
#pragma unroll
            for (int i = 0; i < 8; i++)
#pragma unroll
                for (int j = 0; j < 8; j++) acc[i][j] += ar[i] * br[j];
        }
        __syncthreads();
    }

    if (MASKROW) {
#pragma unroll
        for (int i = 0; i < 8; i++) {
            int il = m0 + ty * 8 + i;
            float rs = 0.f;
#pragma unroll
            for (int j = 0; j < 8; j++) {
                int jl = n0 + tx * 8 + j;
                if (il < jl) acc[i][j] = 0.f;
                rs += acc[i][j];
            }
            atomicAdd(&den[(long long)u * M + il], rs);
        }
    }

#pragma unroll
    for (int i = 0; i < 8; i++) {
        int row = m0 + ty * 8 + i;
        float* cptr = &Cp[(long long)row * ldc + n0 + tx * 8];
        float vals[8];
#pragma unroll
        for (int j = 0; j < 8; j++) {
            float v = acc[i][j];
            if (BIAS) v += bias[n0 + tx * 8 + j];
            vals[j] = v;
        }
        if (ACCUM) {
            float4 o0 = *reinterpret_cast<const float4*>(cptr);
            float4 o1 = *reinterpret_cast<const float4*>(cptr + 4);
            vals[0] += o0.x; vals[1] += o0.y; vals[2] += o0.z; vals[3] += o0.w;
            vals[4] += o1.x; vals[5] += o1.y; vals[6] += o1.z; vals[7] += o1.w;
        }
        *reinterpret_cast<float4*>(cptr) =
            make_float4(vals[0], vals[1], vals[2], vals[3]);
        *reinterpret_cast<float4*>(cptr + 4) =
            make_float4(vals[4], vals[5], vals[6], vals[7]);
    }
}

// ---------------- activations: q=elu(q)+1, k=elu(k*sigmoid(g))+1 -------------
__global__ void act_kernel(float* __restrict__ qkvg) {
    long long idx = (long long)blockIdx.x * 256 + threadIdx.x;  // NROWS*D
    long long row = idx >> 10;
    int d = (int)(idx & 1023);
    float* base = qkvg + row * 4096;
    float q = base[d];
    float k = base[1024 + d];
    float gt = base[3072 + d];
    float sg = 1.f / (1.f + expf(-gt));
    float kg = k * sg;
    q  = (q  > 0.f ? q  : expm1f(q))  + 1.f;
    kg = (kg > 0.f ? kg : expm1f(kg)) + 1.f;
    base[d] = q;
    base[1024 + d] = kg;
}

// ---------------- per-chunk K column sums ------------------------------------
__global__ void ksum_kernel(const float* __restrict__ qkvg, float* __restrict__ pk) {
    int u = blockIdx.x;
    int d = blockIdx.y * 256 + threadIdx.x;
    const float* base = qkvg + (long long)u * CHUNK * 4096 + 1024 + d;
    float s = 0.f;
#pragma unroll 8
    for (int t = 0; t < CHUNK; t++) s += base[(long long)t * 4096];
    pk[u * D_MODEL + d] = s;
}

// ---------------- exclusive prefix over chunks (in place) --------------------
__global__ void prefix_p(float* __restrict__ P) {
    long long e = (long long)blockIdx.x * 256 + threadIdx.x;  // b*2^20 + elem
    int b = (int)(e >> 20);
    long long off = e & 1048575;
    float* base = P + (long long)b * NCHUNK * 1048576 + off;
    float run = 0.f;
#pragma unroll
    for (int c = 0; c < NCHUNK; c++) {
        float t = base[(long long)c * 1048576];
        base[(long long)c * 1048576] = run;
        run += t;
    }
}

__global__ void prefix_k(float* __restrict__ Pk) {
    int e = blockIdx.x * 256 + threadIdx.x;  // b*1024 + d
    int b = e >> 10;
    int d = e & 1023;
    float* base = Pk + b * NCHUNK * D_MODEL + d;
    float run = 0.f;
#pragma unroll
    for (int c = 0; c < NCHUNK; c++) {
        float t = base[c * D_MODEL];
        base[c * D_MODEL] = run;
        run += t;
    }
}

// ---------------- den (inter-chunk part): den[r] = eps + q_r . Sk[u] ---------
__global__ void den_kernel(const float* __restrict__ qkvg,
                           const float* __restrict__ pk,
                           float* __restrict__ den) {
    int warp = blockIdx.x * 8 + (threadIdx.x >> 5);
    int lane = threadIdx.x & 31;
    const float* q  = qkvg + (long long)warp * 4096;
    const float* sk = pk + (warp / CHUNK) * D_MODEL;
    float s = 0.f;
#pragma unroll 8
    for (int i = lane; i < D_MODEL; i += 32) s += q[i] * sk[i];
#pragma unroll
    for (int o = 16; o > 0; o >>= 1) s += __shfl_xor_sync(0xffffffffu, s, o);
    if (lane == 0) den[warp] = s + DEN_EPS;
}

// ---------------- num /= den --------------------------------------------------
__global__ void div_kernel(float* __restrict__ num, const float* __restrict__ den) {
    long long idx = (long long)blockIdx.x * 256 + threadIdx.x;
    num[idx] *= __frcp_rn(den[idx >> 10]);
}

// ---------------- launch ------------------------------------------------------
extern "C" void kernel_launch(void* const* d_in, const int* in_sizes, int n_in,
                              void* d_out, int out_size) {
    const float* x      = (const float*)d_in[0];
    const float* w_qkv  = (const float*)d_in[1];
    const float* b_qkv  = (const float*)d_in[2];
    const float* w_gate = (const float*)d_in[3];
    const float* b_gate = (const float*)d_in[4];
    const float* w_proj = (const float*)d_in[5];
    const float* b_proj = (const float*)d_in[6];
    const float* ln_g   = (const float*)d_in[7];
    const float* ln_b   = (const float*)d_in[8];
    float* out = (float*)d_out;

    float *p_xn, *p_qkvg, *p_P, *p_Pk, *p_attn, *p_num, *p_den;
    cudaGetSymbolAddress((void**)&p_xn,   g_xn);
    cudaGetSymbolAddress((void**)&p_qkvg, g_qkvg);
    cudaGetSymbolAddress((void**)&p_P,    g_P);
    cudaGetSymbolAddress((void**)&p_Pk,   g_Pk);
    cudaGetSymbolAddress((void**)&p_attn, g_attn);
    cudaGetSymbolAddress((void**)&p_num,  g_num);
    cudaGetSymbolAddress((void**)&p_den,  g_den);

    // 1. LayerNorm
    ln_kernel<<<NROWS, 256>>>(x, ln_g, ln_b, p_xn);

    // 2. qkv = xn @ w_qkv + b_qkv   -> g_qkvg[:, 0:3072]
    gemm_kernel<false, false, false, true, false>
        <<<dim3(3072 / 128, NROWS / 128, 1), 256>>>(
            p_xn, D_MODEL, 0, w_qkv, 3072, 0,
            p_qkvg, 4096, 0, b_qkv, nullptr, NROWS, 3072, D_MODEL);

    // 3. gate_pre = xn @ w_gate + b_gate -> g_qkvg[:, 3072:4096]
    gemm_kernel<false, false, false, true, false>
        <<<dim3(1024 / 128, NROWS / 128, 1), 256>>>(
            p_xn, D_MODEL, 0, w_gate, 1024, 0,
            p_qkvg + 3072, 4096, 0, b_gate, nullptr, NROWS, 1024, D_MODEL);

    // 4. activations in place
    act_kernel<<<(NROWS * D_MODEL) / 256, 256>>>(p_qkvg);

    // 5. per-chunk K colsums
    ksum_kernel<<<dim3(NUNITS, D_MODEL / 256), 256>>>(p_qkvg, p_Pk);

    // 6. P_u = K_u^T @ V_u   (batched over 64 units)
    gemm_kernel<true, false, false, false, false>
        <<<dim3(8, 8, NUNITS), 256>>>(
            p_qkvg + 1024, 4096, (long long)CHUNK * 4096,
            p_qkvg + 2048, 4096, (long long)CHUNK * 4096,
            p_P, D_MODEL, (long long)D_MODEL * D_MODEL,
            nullptr, nullptr, D_MODEL, D_MODEL, CHUNK);

    // 7. exclusive prefix scans over chunks
    prefix_p<<<(B_SZ * 1048576) / 256, 256>>>(p_P);
    prefix_k<<<(B_SZ * D_MODEL) / 256, 256>>>(p_Pk);

    // 8. den = eps + q . Sk   (writes all of g_den; must precede attn atomics)
    den_kernel<<<NROWS / 8, 256>>>(p_qkvg, p_Pk, p_den);

    // 9. num = Q_u @ S_u  (batched)
    gemm_kernel<false, false, false, false, false>
        <<<dim3(8, 2, NUNITS), 256>>>(
            p_qkvg, 4096, (long long)CHUNK * 4096,
            p_P, D_MODEL, (long long)D_MODEL * D_MODEL,
            p_num, D_MODEL, (long long)CHUNK * D_MODEL,
            nullptr, nullptr, CHUNK, D_MODEL, D_MODEL);

    // 10. attn_u = tril(Q_u @ K_u^T), rowsums atomically into den
    gemm_kernel<false, true, false, false, true>
        <<<dim3(2, 2, NUNITS), 256>>>(
            p_qkvg, 4096, (long long)CHUNK * 4096,
            p_qkvg + 1024, 4096, (long long)CHUNK * 4096,
            p_attn, CHUNK, (long long)CHUNK * CHUNK,
            nullptr, p_den, CHUNK, CHUNK, D_MODEL);

    // 11. num += attn_u @ V_u
    gemm_kernel<false, false, true, false, false>
        <<<dim3(8, 2, NUNITS), 256>>>(
            p_attn, CHUNK, (long long)CHUNK * CHUNK,
            p_qkvg + 2048, 4096, (long long)CHUNK * 4096,
            p_num, D_MODEL, (long long)CHUNK * D_MODEL,
            nullptr, nullptr, CHUNK, D_MODEL, CHUNK);

    // 12. num /= den
    div_kernel<<<(NROWS * D_MODEL) / 256, 256>>>(p_num, p_den);

    // 13. out = num @ w_proj + b_proj
    gemm_kernel<false, false, false, true, false>
        <<<dim3(1024 / 128, NROWS / 128, 1), 256>>>(
            p_num, D_MODEL, 0, w_proj, 1024, 0,
            out, 1024, 0, b_proj, nullptr, NROWS, 1024, D_MODEL);
}

// round 3
// speedup vs baseline: 2.6705x; 2.6705x over previous
#include <cuda_runtime.h>
#include <cstdint>
#include <math.h>

#define D_MODEL 1024
#define B_SZ 4
#define T_SZ 4096
#define NROWS (B_SZ * T_SZ)          /* 16384 */
#define CHUNK 256
#define NCHUNK (T_SZ / CHUNK)        /* 16 */
#define NUNITS (B_SZ * NCHUNK)       /* 64 */
#define LN_EPS 1e-5f
#define DEN_EPS 1e-6f

// ---------------- scratch (device globals; no allocations allowed) -----------
__device__ float g_xn[(size_t)NROWS * D_MODEL];                 // 64 MB
__device__ float g_qkvg[(size_t)NROWS * 4 * D_MODEL];           // 256 MB  q|k|v|gate
__device__ float g_P[(size_t)NUNITS * D_MODEL * D_MODEL];       // 256 MB  Pt = V^T K per chunk -> excl prefix
__device__ float g_Pk[NUNITS * D_MODEL];                        // chunk K colsums -> excl prefix
__device__ float g_attn[(size_t)NUNITS * CHUNK * CHUNK];        // 16.8 MB
__device__ float g_num[(size_t)NROWS * D_MODEL];                // 64 MB
__device__ float g_den[NROWS];
__device__ float g_wt[(size_t)4096 * 1024];                     // packed qkv|gate weights, [n][k], tf32
__device__ float g_wpT[(size_t)1024 * 1024];                    // w_proj^T [n][k], tf32
__device__ float g_bcat[4096];

// ---------------- small helpers ----------------------------------------------
__device__ __forceinline__ float tf32r(float x) {
    uint32_t u;
    asm("cvt.rna.tf32.f32 %0, %1;" : "=r"(u) : "f"(x));
    return __uint_as_float(u);
}

__device__ __forceinline__ uint32_t smem_u32(const void* p) {
    uint32_t a;
    asm("{ .reg .u64 t; cvta.to.shared.u64 t, %1; cvt.u32.u64 %0, t; }" : "=r"(a) : "l"(p));
    return a;
}

#define CP16(dst, src) \
    asm volatile("cp.async.cg.shared.global [%0], [%1], 16;" :: "r"(dst), "l"(src))
#define CP4(dst, src) \
    asm volatile("cp.async.ca.shared.global [%0], [%1], 4;" :: "r"(dst), "l"(src))
#define CP_COMMIT() asm volatile("cp.async.commit_group;" ::: "memory")
#define CP_WAIT(n)  asm volatile("cp.async.wait_group %0;" :: "n"(n) : "memory")

// ---------------- mma.sync tf32 GEMM ------------------------------------------
// Block tile 128x128, 8 warps (2 in M x 4 in N), warp tile 64x32.
// mma.m16n8k8 tf32: per warp 4 m-tiles x 4 n-tiles. K-tile = 32, double-buffered.
// Shared layout: rows padded to 36 floats (conflict-free for frag patterns).
// AT/BT: 0 = operand stored [rows][k] K-major; 1 = stored [k][rows].
// EPI: 0 plain, 1 +bias, 2 accumulate into C, 3 causal mask + tf32 round + rowsum->den.
#define PADK 36
#define ABUF 4608              /* 128*36 floats per buffer */
#define SMEM_BYTES (4 * ABUF * 4)   /* 73728 B */

template <int AT, int BT, int EPI>
__global__ void __launch_bounds__(256) tgemm(
    const float* __restrict__ A, int lda, long long sA,
    const float* __restrict__ B, int ldb, long long sB,
    float* __restrict__ C, int ldc, long long sC,
    const float* __restrict__ bias, float* __restrict__ den, int K) {
    extern __shared__ float sm[];
    const uint32_t su = smem_u32(sm);
    const int tid = threadIdx.x;
    const int u = blockIdx.z;
    const float* Ab = A + (long long)u * sA;
    const float* Bb = B + (long long)u * sB;
    float* Cb = C + (long long)u * sC;
    const int m0 = blockIdx.y * 128;
    const int n0 = blockIdx.x * 128;

    const int lane = tid & 31;
    const int w = tid >> 5;
    const int wm = (w & 1) * 64;      // warp row base
    const int wn = (w >> 1) * 32;     // warp col base
    const int l4 = lane >> 2;
    const int lm = lane & 3;

    auto loadA = [&](int buf, int kt) {
        uint32_t dst = su + buf * (ABUF * 4);
        int k0 = kt * 32;
        if (AT == 0) {
#pragma unroll
            for (int p = 0; p < 4; p++) {
                int c = tid + p * 256;
                int row = c >> 3, ch = c & 7;
                const float* src = Ab + (long long)(m0 + row) * lda + k0 + ch * 4;
                CP16(dst + (row * PADK + ch * 4) * 4, src);
            }
        } else {
#pragma unroll
            for (int p = 0; p < 16; p++) {
                int e = tid + p * 256;
                int k = e >> 7, m = e & 127;
                const float* src = Ab + (long long)(k0 + k) * lda + m0 + m;
                CP4(dst + (m * PADK + k) * 4, src);
            }
        }
    };
    auto loadB = [&](int buf, int kt) {
        uint32_t dst = su + (2 * ABUF + buf * ABUF) * 4;
        int k0 = kt * 32;
        if (BT == 0) {
#pragma unroll
            for (int p = 0; p < 4; p++) {
                int c = tid + p * 256;
                int row = c >> 3, ch = c & 7;
                const float* src = Bb + (long long)(n0 + row) * ldb + k0 + ch * 4;
                CP16(dst + (row * PADK + ch * 4) * 4, src);
            }
        } else {
#pragma unroll
            for (int p = 0; p < 16; p++) {
                int e = tid + p * 256;
                int k = e >> 7, n = e & 127;
                const float* src = Bb + (long long)(k0 + k) * ldb + n0 + n;
                CP4(dst + (n * PADK + k) * 4, src);
            }
        }
    };

    float c[4][4][4];
#pragma unroll
    for (int mt = 0; mt < 4; mt++)
#pragma unroll
        for (int nt = 0; nt < 4; nt++)
#pragma unroll
            for (int r = 0; r < 4; r++) c[mt][nt][r] = 0.f;

    const int KT = K >> 5;
    loadA(0, 0);
    loadB(0, 0);
    CP_COMMIT();

    for (int i = 0; i < KT; i++) {
        if (i + 1 < KT) {
            loadA((i + 1) & 1, i + 1);
            loadB((i + 1) & 1, i + 1);
            CP_COMMIT();
            CP_WAIT(1);
        } else {
            CP_WAIT(0);
        }
        __syncthreads();

        const float* Sa = sm + (i & 1) * ABUF;
        const float* Sb = sm + 2 * ABUF + (i & 1) * ABUF;
#pragma unroll
        for (int kk = 0; kk < 32; kk += 8) {
            uint32_t af[4][4], bf[4][2];
#pragma unroll
            for (int mt = 0; mt < 4; mt++) {
                const float* ap = Sa + (wm + mt * 16 + l4) * PADK + kk + lm;
                af[mt][0] = __float_as_uint(ap[0]);
                af[mt][1] = __float_as_uint(ap[8 * PADK]);
                af[mt][2] = __float_as_uint(ap[4]);
                af[mt][3] = __float_as_uint(ap[8 * PADK + 4]);
            }
#pragma unroll
            for (int nt = 0; nt < 4; nt++) {
                const float* bp = Sb + (wn + nt * 8 + l4) * PADK + kk + lm;
                bf[nt][0] = __float_as_uint(bp[0]);
                bf[nt][1] = __float_as_uint(bp[4]);
            }
#pragma unroll
            for (int mt = 0; mt < 4; mt++)
#pragma unroll
                for (int nt = 0; nt < 4; nt++)
                    asm volatile(
                        "mma.sync.aligned.m16n8k8.row.col.f32.tf32.tf32.f32 "
                        "{%0,%1,%2,%3}, {%4,%5,%6,%7}, {%8,%9}, {%0,%1,%2,%3};"
                        : "+f"(c[mt][nt][0]), "+f"(c[mt][nt][1]),
                          "+f"(c[mt][nt][2]), "+f"(c[mt][nt][3])
                        : "r"(af[mt][0]), "r"(af[mt][1]), "r"(af[mt][2]), "r"(af[mt][3]),
                          "r"(bf[nt][0]), "r"(bf[nt][1]));
        }
        __syncthreads();
    }

    // ---- epilogue ----
#pragma unroll
    for (int mt = 0; mt < 4; mt++) {
        int row0 = m0 + wm + mt * 16 + l4;
        int row1 = row0 + 8;
        float rs0 = 0.f, rs1 = 0.f;
#pragma unroll
        for (int nt = 0; nt < 4; nt++) {
            int col = n0 + wn + nt * 8 + lm * 2;
            float v0 = c[mt][nt][0], v1 = c[mt][nt][1];
            float v2 = c[mt][nt][2], v3 = c[mt][nt][3];
            float* p0 = Cb + (long long)row0 * ldc + col;
            float* p1 = Cb + (long long)row1 * ldc + col;
            if (EPI == 1) {
                float b0 = bias[col], b1 = bias[col + 1];
                v0 += b0; v1 += b1; v2 += b0; v3 += b1;
            }
            if (EPI == 2) {
                float2 o0 = *reinterpret_cast<const float2*>(p0);
                float2 o1 = *reinterpret_cast<const float2*>(p1);
                v0 += o0.x; v1 += o0.y; v2 += o1.x; v3 += o1.y;
            }
            if (EPI == 3) {
                v0 = (col     > row0) ? 0.f : tf32r(v0);
                v1 = (col + 1 > row0) ? 0.f : tf32r(v1);
                v2 = (col     > row1) ? 0.f : tf32r(v2);
                v3 = (col + 1 > row1) ? 0.f : tf32r(v3);
                rs0 += v0 + v1;
                rs1 += v2 + v3;
            }
            *reinterpret_cast<float2*>(p0) = make_float2(v0, v1);
            *reinterpret_cast<float2*>(p1) = make_float2(v2, v3);
        }
        if (EPI == 3) {
            rs0 += __shfl_xor_sync(0xffffffffu, rs0, 1);
            rs0 += __shfl_xor_sync(0xffffffffu, rs0, 2);
            rs1 += __shfl_xor_sync(0xffffffffu, rs1, 1);
            rs1 += __shfl_xor_sync(0xffffffffu, rs1, 2);
            if (lm == 0) {
                atomicAdd(den + (long long)u * CHUNK + row0, rs0);
                atomicAdd(den + (long long)u * CHUNK + row1, rs1);
            }
        }
    }
}

// ---------------- LayerNorm (store tf32-rounded) ------------------------------
__global__ void ln_kernel(const float* __restrict__ x,
                          const float* __restrict__ g,
                          const float* __restrict__ b,
                          float* __restrict__ xn) {
    int row = blockIdx.x;
    const float* xr = x + (size_t)row * D_MODEL;
    float* outr = xn + (size_t)row * D_MODEL;
    int tid = threadIdx.x;

    float vals[4];
    float s = 0.f, ss = 0.f;
#pragma unroll
    for (int i = 0; i < 4; i++) {
        float v = xr[tid + i * 256];
        vals[i] = v;
        s += v;
        ss += v * v;
    }
#pragma unroll
    for (int o = 16; o > 0; o >>= 1) {
        s  += __shfl_xor_sync(0xffffffffu, s, o);
        ss += __shfl_xor_sync(0xffffffffu, ss, o);
    }
    __shared__ float sbuf[8], ssbuf[8];
    int warp = tid >> 5, lane = tid & 31;
    if (lane == 0) { sbuf[warp] = s; ssbuf[warp] = ss; }
    __syncthreads();
    float ts = 0.f, tss = 0.f;
#pragma unroll
    for (int wq = 0; wq < 8; wq++) { ts += sbuf[wq]; tss += ssbuf[wq]; }
    float mu = ts * (1.0f / D_MODEL);
    float var = tss * (1.0f / D_MODEL) - mu * mu;
    float inv = rsqrtf(var + LN_EPS);
#pragma unroll
    for (int i = 0; i < 4; i++) {
        int d = tid + i * 256;
        outr[d] = tf32r((vals[i] - mu) * inv * g[d] + b[d]);
    }
}

// ---------------- weight prepack ----------------------------------------------
__global__ void pack_w(const float* __restrict__ wq, const float* __restrict__ wg,
                       float* __restrict__ wt) {
    long long idx = (long long)blockIdx.x * 256 + threadIdx.x;  // n*1024 + k
    int n = (int)(idx >> 10);
    int k = (int)(idx & 1023);
    float v = (n < 3072) ? wq[(long long)k * 3072 + n] : wg[(long long)k * 1024 + n - 3072];
    wt[idx] = tf32r(v);
}
__global__ void pack_bias(const float* __restrict__ bq, const float* __restrict__ bg,
                          float* __restrict__ bc) {
    int n = blockIdx.x * 256 + threadIdx.x;
    bc[n] = (n < 3072) ? bq[n] : bg[n - 3072];
}
__global__ void pack_wp(const float* __restrict__ wp, float* __restrict__ wpT) {
    long long idx = (long long)blockIdx.x * 256 + threadIdx.x;  // n*1024 + k
    int n = (int)(idx >> 10);
    int k = (int)(idx & 1023);
    wpT[idx] = tf32r(wp[(long long)k * 1024 + n]);
}

// ---------------- activations: q=elu(q)+1, k=elu(k*sigmoid(g))+1, round v ----
__global__ void act_kernel(float* __restrict__ qkvg) {
    long long idx = (long long)blockIdx.x * 256 + threadIdx.x;
    long long row = idx >> 10;
    int d = (int)(idx & 1023);
    float* base = qkvg + row * 4096;
    float q = base[d];
    float k = base[1024 + d];
    float v = base[2048 + d];
    float gt = base[3072 + d];
    float sg = 1.f / (1.f + expf(-gt));
    float kg = k * sg;
    q  = (q  > 0.f ? q  : expm1f(q))  + 1.f;
    kg = (kg > 0.f ? kg : expm1f(kg)) + 1.f;
    base[d] = tf32r(q);
    base[1024 + d] = tf32r(kg);
    base[2048 + d] = tf32r(v);
}

// ---------------- per-chunk K column sums ------------------------------------
__global__ void ksum_kernel(const float* __restrict__ qkvg, float* __restrict__ pk) {
    int u = blockIdx.x;
    int d = blockIdx.y * 256 + threadIdx.x;
    const float* base = qkvg + (long long)u * CHUNK * 4096 + 1024 + d;
    float s = 0.f;
#pragma unroll 8
    for (int t = 0; t < CHUNK; t++) s += base[(long long)t * 4096];
    pk[u * D_MODEL + d] = s;
}

// ---------------- exclusive prefix over chunks (in place, round stores) ------
__global__ void prefix_p(float* __restrict__ P) {
    long long e = (long long)blockIdx.x * 256 + threadIdx.x;
    int b = (int)(e >> 20);
    long long off = e & 1048575;
    float* base = P + (long long)b * NCHUNK * 1048576 + off;
    float run = 0.f;
#pragma unroll
    for (int c = 0; c < NCHUNK; c++) {
        float t = base[(long long)c * 1048576];
        base[(long long)c * 1048576] = tf32r(run);
        run += t;
    }
}

__global__ void prefix_k(float* __restrict__ Pk) {
    int e = blockIdx.x * 256 + threadIdx.x;
    int b = e >> 10;
    int d = e & 1023;
    float* base = Pk + b * NCHUNK * D_MODEL + d;
    float run = 0.f;
#pragma unroll
    for (int c = 0; c < NCHUNK; c++) {
        float t = base[c * D_MODEL];
        base[c * D_MODEL] = run;
        run += t;
    }
}

// ---------------- den (inter-chunk part): den[r] = eps + q_r . Sk[u] ---------
__global__ void den_kernel(const float* __restrict__ qkvg,
                           const float* __restrict__ pk,
                           float* __restrict__ den) {
    int warp = blockIdx.x * 8 + (threadIdx.x >> 5);
    int lane = threadIdx.x & 31;
    const float* q  = qkvg + (long long)warp * 4096;
    const float* sk = pk + (warp / CHUNK) * D_MODEL;
    float s = 0.f;
#pragma unroll 8
    for (int i = lane; i < D_MODEL; i += 32) s += q[i] * sk[i];
#pragma unroll
    for (int o = 16; o > 0; o >>= 1) s += __shfl_xor_sync(0xffffffffu, s, o);
    if (lane == 0) den[warp] = s + DEN_EPS;
}

// ---------------- num = round(num / den) --------------------------------------
__global__ void div_kernel(float* __restrict__ num, const float* __restrict__ den) {
    long long idx = (long long)blockIdx.x * 256 + threadIdx.x;
    num[idx] = tf32r(num[idx] * __frcp_rn(den[idx >> 10]));
}

// ---------------- launch ------------------------------------------------------
extern "C" void kernel_launch(void* const* d_in, const int* in_sizes, int n_in,
                              void* d_out, int out_size) {
    const float* x      = (const float*)d_in[0];
    const float* w_qkv  = (const float*)d_in[1];
    const float* b_qkv  = (const float*)d_in[2];
    const float* w_gate = (const float*)d_in[3];
    const float* b_gate = (const float*)d_in[4];
    const float* w_proj = (const float*)d_in[5];
    const float* b_proj = (const float*)d_in[6];
    const float* ln_g   = (const float*)d_in[7];
    const float* ln_b   = (const float*)d_in[8];
    float* out = (float*)d_out;

    float *p_xn, *p_qkvg, *p_P, *p_Pk, *p_attn, *p_num, *p_den, *p_wt, *p_wpT, *p_bcat;
    cudaGetSymbolAddress((void**)&p_xn,   g_xn);
    cudaGetSymbolAddress((void**)&p_qkvg, g_qkvg);
    cudaGetSymbolAddress((void**)&p_P,    g_P);
    cudaGetSymbolAddress((void**)&p_Pk,   g_Pk);
    cudaGetSymbolAddress((void**)&p_attn, g_attn);
    cudaGetSymbolAddress((void**)&p_num,  g_num);
    cudaGetSymbolAddress((void**)&p_den,  g_den);
    cudaGetSymbolAddress((void**)&p_wt,   g_wt);
    cudaGetSymbolAddress((void**)&p_wpT,  g_wpT);
    cudaGetSymbolAddress((void**)&p_bcat, g_bcat);

    cudaFuncSetAttribute(tgemm<0, 0, 1>, cudaFuncAttributeMaxDynamicSharedMemorySize, SMEM_BYTES);
    cudaFuncSetAttribute(tgemm<1, 1, 0>, cudaFuncAttributeMaxDynamicSharedMemorySize, SMEM_BYTES);
    cudaFuncSetAttribute(tgemm<0, 0, 0>, cudaFuncAttributeMaxDynamicSharedMemorySize, SMEM_BYTES);
    cudaFuncSetAttribute(tgemm<0, 0, 3>, cudaFuncAttributeMaxDynamicSharedMemorySize, SMEM_BYTES);
    cudaFuncSetAttribute(tgemm<0, 1, 2>, cudaFuncAttributeMaxDynamicSharedMemorySize, SMEM_BYTES);

    // 0. prepack weights (tf32 round + transpose; qkv||gate fused)
    pack_w   <<<(4096 * 1024) / 256, 256>>>(w_qkv, w_gate, p_wt);
    pack_bias<<<4096 / 256, 256>>>(b_qkv, b_gate, p_bcat);
    pack_wp  <<<(1024 * 1024) / 256, 256>>>(w_proj, p_wpT);

    // 1. LayerNorm (tf32-rounded xn)
    ln_kernel<<<NROWS, 256>>>(x, ln_g, ln_b, p_xn);

    // 2. qkvg = xn @ [w_qkv|w_gate] + bias   -> g_qkvg [16384 x 4096]
    tgemm<0, 0, 1><<<dim3(4096 / 128, NROWS / 128, 1), 256, SMEM_BYTES>>>(
        p_xn, D_MODEL, 0, p_wt, D_MODEL, 0,
        p_qkvg, 4096, 0, p_bcat, nullptr, D_MODEL);

    // 3. activations (q, gated k, rounded v)
    act_kernel<<<(NROWS * D_MODEL) / 256, 256>>>(p_qkvg);

    // 4. per-chunk K colsums
    ksum_kernel<<<dim3(NUNITS, D_MODEL / 256), 256>>>(p_qkvg, p_Pk);

    // 5. Pt_u = V_u^T @ K_u  (stored [d2][d1], batched over units)
    tgemm<1, 1, 0><<<dim3(D_MODEL / 128, D_MODEL / 128, NUNITS), 256, SMEM_BYTES>>>(
        p_qkvg + 2048, 4096, (long long)CHUNK * 4096,
        p_qkvg + 1024, 4096, (long long)CHUNK * 4096,
        p_P, D_MODEL, (long long)D_MODEL * D_MODEL,
        nullptr, nullptr, CHUNK);

    // 6. exclusive prefix scans over chunks
    prefix_p<<<(B_SZ * 1048576) / 256, 256>>>(p_P);
    prefix_k<<<(B_SZ * D_MODEL) / 256, 256>>>(p_Pk);

    // 7. den = eps + q . Sk   (must precede masked-attn atomics)
    den_kernel<<<NROWS / 8, 256>>>(p_qkvg, p_Pk, p_den);

    // 8. num = Q_u @ S_u   (B = Pt prefix, K-major direct)
    tgemm<0, 0, 0><<<dim3(D_MODEL / 128, CHUNK / 128, NUNITS), 256, SMEM_BYTES>>>(
        p_qkvg, 4096, (long long)CHUNK * 4096,
        p_P, D_MODEL, (long long)D_MODEL * D_MODEL,
        p_num, D_MODEL, (long long)CHUNK * D_MODEL,
        nullptr, nullptr, D_MODEL);

    // 9. attn_u = tril(Q_u @ K_u^T), rounded; rowsums atomically into den
    tgemm<0, 0, 3><<<dim3(CHUNK / 128, CHUNK / 128, NUNITS), 256, SMEM_BYTES>>>(
        p_qkvg, 4096, (long long)CHUNK * 4096,
        p_qkvg + 1024, 4096, (long long)CHUNK * 4096,
        p_attn, CHUNK, (long long)CHUNK * CHUNK,
        nullptr, p_den, D_MODEL);

    // 10. num += attn_u @ V_u
    tgemm<0, 1, 2><<<dim3(D_MODEL / 128, CHUNK / 128, NUNITS), 256, SMEM_BYTES>>>(
        p_attn, CHUNK, (long long)CHUNK * CHUNK,
        p_qkvg + 2048, 4096, (long long)CHUNK * 4096,
        p_num, D_MODEL, (long long)CHUNK * D_MODEL,
        nullptr, nullptr, CHUNK);

    // 11. num = round(num / den)
    div_kernel<<<(NROWS * D_MODEL) / 256, 256>>>(p_num, p_den);

    // 12. out = num @ w_proj + b_proj
    tgemm<0, 0, 1><<<dim3(D_MODEL / 128, NROWS / 128, 1), 256, SMEM_BYTES>>>(
        p_num, D_MODEL, 0, p_wpT, D_MODEL, 0,
        out, D_MODEL, 0, b_proj, nullptr, D_MODEL);
}

// round 4
// speedup vs baseline: 3.0551x; 1.1440x over previous
#include <cuda_runtime.h>
#include <cstdint>
#include <math.h>

#define D_MODEL 1024
#define B_SZ 4
#define T_SZ 4096
#define NROWS (B_SZ * T_SZ)          /* 16384 */
#define CHUNK 256
#define NCHUNK (T_SZ / CHUNK)        /* 16 */
#define NUNITS (B_SZ * NCHUNK)       /* 64 */
#define LN_EPS 1e-5f
#define DEN_EPS 1e-6f

// ---------------- scratch (device globals; no allocations allowed) -----------
__device__ float g_xn[(size_t)NROWS * D_MODEL];                 // 64 MB
__device__ float g_qkvg[(size_t)NROWS * 4 * D_MODEL];           // 256 MB  q|k|v|gate
__device__ float g_P[(size_t)NUNITS * D_MODEL * D_MODEL];       // 256 MB  Pt = V^T K per chunk -> excl prefix
__device__ float g_Pk[NUNITS * D_MODEL];                        // chunk K colsums -> excl prefix
__device__ float g_attn[(size_t)NUNITS * CHUNK * CHUNK];        // 16.8 MB
__device__ float g_num[(size_t)NROWS * D_MODEL];                // 64 MB
__device__ float g_den[NROWS];
__device__ float g_wt[(size_t)4096 * 1024];                     // packed qkv|gate weights, [n][k], tf32
__device__ float g_wpT[(size_t)1024 * 1024];                    // w_proj^T [n][k], tf32
__device__ float g_bcat[4096];

// ---------------- small helpers ----------------------------------------------
__device__ __forceinline__ float tf32r(float x) {
    uint32_t u;
    asm("cvt.rna.tf32.f32 %0, %1;" : "=r"(u) : "f"(x));
    return __uint_as_float(u);
}

__device__ __forceinline__ uint32_t smem_u32(const void* p) {
    uint32_t a;
    asm("{ .reg .u64 t; cvta.to.shared.u64 t, %1; cvt.u32.u64 %0, t; }" : "=r"(a) : "l"(p));
    return a;
}

#define CP16(dst, src) \
    asm volatile("cp.async.cg.shared.global [%0], [%1], 16;" :: "r"(dst), "l"(src))
#define CP4(dst, src) \
    asm volatile("cp.async.ca.shared.global [%0], [%1], 4;" :: "r"(dst), "l"(src))
#define CP_COMMIT() asm volatile("cp.async.commit_group;" ::: "memory")
#define CP_WAIT(n)  asm volatile("cp.async.wait_group %0;" :: "n"(n) : "memory")

// ---------------- mma.sync tf32 GEMM ------------------------------------------
// Block tile 128x128, 8 warps (2 in M x 4 in N), warp tile 64x32.
// mma.m16n8k8 tf32. K-tile = 32, 3-stage cp.async pipeline, one sync per tile.
// Shared layout: rows padded to 36 floats (conflict-free for frag patterns).
// AT/BT: 0 = operand stored [rows][k] K-major; 1 = stored [k][rows].
// EPI: 0 plain, 1 +bias, 2 accumulate, 3 causal mask + round + rowsum->den,
//      4 (old + acc) * rcp(den) + round  (fused div for attn@V).
#define PADK 36
#define TBUF 4608              /* 128*36 floats: one operand, one stage */
#define STAGEF 9216            /* floats per stage (A+B) */
#define SMEM_BYTES (3 * STAGEF * 4)   /* 110592 B */

template <int AT, int BT, int EPI>
__global__ void __launch_bounds__(256, 2) tgemm(
    const float* __restrict__ A, int lda, long long sA,
    const float* __restrict__ B, int ldb, long long sB,
    float* __restrict__ C, int ldc, long long sC,
    const float* __restrict__ bias, float* __restrict__ den, int K) {
    extern __shared__ float sm[];
    const uint32_t su = smem_u32(sm);
    const int tid = threadIdx.x;
    const int u = blockIdx.z;
    const float* Ab = A + (long long)u * sA;
    const float* Bb = B + (long long)u * sB;
    float* Cb = C + (long long)u * sC;
    const int m0 = blockIdx.y * 128;
    const int n0 = blockIdx.x * 128;

    const int lane = tid & 31;
    const int w = tid >> 5;
    const int wm = (w & 1) * 64;      // warp row base
    const int wn = (w >> 1) * 32;     // warp col base
    const int l4 = lane >> 2;
    const int lm = lane & 3;

    auto loadA = [&](int st, int kt) {
        uint32_t dst = su + st * (STAGEF * 4);
        int k0 = kt * 32;
        if (AT == 0) {
#pragma unroll
            for (int p = 0; p < 4; p++) {
                int c = tid + p * 256;
                int row = c >> 3, ch = c & 7;
                const float* src = Ab + (long long)(m0 + row) * lda + k0 + ch * 4;
                CP16(dst + (row * PADK + ch * 4) * 4, src);
            }
        } else {
#pragma unroll
            for (int p = 0; p < 16; p++) {
                int e = tid + p * 256;
                int k = e >> 7, m = e & 127;
                const float* src = Ab + (long long)(k0 + k) * lda + m0 + m;
                CP4(dst + (m * PADK + k) * 4, src);
            }
        }
    };
    auto loadB = [&](int st, int kt) {
        uint32_t dst = su + (st * STAGEF + TBUF) * 4;
        int k0 = kt * 32;
        if (BT == 0) {
#pragma unroll
            for (int p = 0; p < 4; p++) {
                int c = tid + p * 256;
                int row = c >> 3, ch = c & 7;
                const float* src = Bb + (long long)(n0 + row) * ldb + k0 + ch * 4;
                CP16(dst + (row * PADK + ch * 4) * 4, src);
            }
        } else {
#pragma unroll
            for (int p = 0; p < 16; p++) {
                int e = tid + p * 256;
                int k = e >> 7, n = e & 127;
                const float* src = Bb + (long long)(k0 + k) * ldb + n0 + n;
                CP4(dst + (n * PADK + k) * 4, src);
            }
        }
    };

    float c[4][4][4];
#pragma unroll
    for (int mt = 0; mt < 4; mt++)
#pragma unroll
        for (int nt = 0; nt < 4; nt++)
#pragma unroll
            for (int r = 0; r < 4; r++) c[mt][nt][r] = 0.f;

    const int KT = K >> 5;
    loadA(0, 0); loadB(0, 0); CP_COMMIT();
    if (KT > 1) { loadA(1, 1); loadB(1, 1); CP_COMMIT(); }
    else        { CP_COMMIT(); }   // keep group count aligned

    int st = 0;                    // stage of tile i
    int stn = (KT > 2) ? 2 : 0;    // stage to fill next
    for (int i = 0; i < KT; i++) {
        if (i < KT - 1) { CP_WAIT(1); } else { CP_WAIT(0); }
        __syncthreads();

        if (i + 2 < KT) {
            loadA(stn, i + 2);
            loadB(stn, i + 2);
            CP_COMMIT();
            stn = (stn == 2) ? 0 : stn + 1;
        }

        const float* Sa = sm + st * STAGEF;
        const float* Sb = sm + st * STAGEF + TBUF;
        st = (st == 2) ? 0 : st + 1;
#pragma unroll
        for (int kk = 0; kk < 32; kk += 8) {
            uint32_t af[4][4], bf[4][2];
#pragma unroll
            for (int mt = 0; mt < 4; mt++) {
                const float* ap = Sa + (wm + mt * 16 + l4) * PADK + kk + lm;
                af[mt][0] = __float_as_uint(ap[0]);
                af[mt][1] = __float_as_uint(ap[8 * PADK]);
                af[mt][2] = __float_as_uint(ap[4]);
                af[mt][3] = __float_as_uint(ap[8 * PADK + 4]);
            }
#pragma unroll
            for (int nt = 0; nt < 4; nt++) {
                const float* bp = Sb + (wn + nt * 8 + l4) * PADK + kk + lm;
                bf[nt][0] = __float_as_uint(bp[0]);
                bf[nt][1] = __float_as_uint(bp[4]);
            }
#pragma unroll
            for (int mt = 0; mt < 4; mt++)
#pragma unroll
                for (int nt = 0; nt < 4; nt++)
                    asm volatile(
                        "mma.sync.aligned.m16n8k8.row.col.f32.tf32.tf32.f32 "
                        "{%0,%1,%2,%3}, {%4,%5,%6,%7}, {%8,%9}, {%0,%1,%2,%3};"
                        : "+f"(c[mt][nt][0]), "+f"(c[mt][nt][1]),
                          "+f"(c[mt][nt][2]), "+f"(c[mt][nt][3])
                        : "r"(af[mt][0]), "r"(af[mt][1]), "r"(af[mt][2]), "r"(af[mt][3]),
                          "r"(bf[nt][0]), "r"(bf[nt][1]));
        }
    }

    // ---- epilogue ----
#pragma unroll
    for (int mt = 0; mt < 4; mt++) {
        int row0 = m0 + wm + mt * 16 + l4;
        int row1 = row0 + 8;
        float rs0 = 0.f, rs1 = 0.f;
        float rcp0 = 0.f, rcp1 = 0.f;
        if (EPI == 4) {
            rcp0 = __frcp_rn(den[(long long)u * CHUNK + row0]);
            rcp1 = __frcp_rn(den[(long long)u * CHUNK + row1]);
        }
#pragma unroll
        for (int nt = 0; nt < 4; nt++) {
            int col = n0 + wn + nt * 8 + lm * 2;
            float v0 = c[mt][nt][0], v1 = c[mt][nt][1];
            float v2 = c[mt][nt][2], v3 = c[mt][nt][3];
            float* p0 = Cb + (long long)row0 * ldc + col;
            float* p1 = Cb + (long long)row1 * ldc + col;
            if (EPI == 1) {
                float b0 = bias[col], b1 = bias[col + 1];
                v0 += b0; v1 += b1; v2 += b0; v3 += b1;
            }
            if (EPI == 2 || EPI == 4) {
                float2 o0 = *reinterpret_cast<const float2*>(p0);
                float2 o1 = *reinterpret_cast<const float2*>(p1);
                v0 += o0.x; v1 += o0.y; v2 += o1.x; v3 += o1.y;
            }
            if (EPI == 4) {
                v0 = tf32r(v0 * rcp0); v1 = tf32r(v1 * rcp0);
                v2 = tf32r(v2 * rcp1); v3 = tf32r(v3 * rcp1);
            }
            if (EPI == 3) {
                v0 = (col     > row0) ? 0.f : tf32r(v0);
                v1 = (col + 1 > row0) ? 0.f : tf32r(v1);
                v2 = (col     > row1) ? 0.f : tf32r(v2);
                v3 = (col + 1 > row1) ? 0.f : tf32r(v3);
                rs0 += v0 + v1;
                rs1 += v2 + v3;
            }
            *reinterpret_cast<float2*>(p0) = make_float2(v0, v1);
            *reinterpret_cast<float2*>(p1) = make_float2(v2, v3);
        }
        if (EPI == 3) {
            rs0 += __shfl_xor_sync(0xffffffffu, rs0, 1);
            rs0 += __shfl_xor_sync(0xffffffffu, rs0, 2);
            rs1 += __shfl_xor_sync(0xffffffffu, rs1, 1);
            rs1 += __shfl_xor_sync(0xffffffffu, rs1, 2);
            if (lm == 0) {
                atomicAdd(den + (long long)u * CHUNK + row0, rs0);
                atomicAdd(den + (long long)u * CHUNK + row1, rs1);
            }
        }
    }
}

// ---------------- LayerNorm (store tf32-rounded) ------------------------------
__global__ void ln_kernel(const float* __restrict__ x,
                          const float* __restrict__ g,
                          const float* __restrict__ b,
                          float* __restrict__ xn) {
    int row = blockIdx.x;
    const float* xr = x + (size_t)row * D_MODEL;
    float* outr = xn + (size_t)row * D_MODEL;
    int tid = threadIdx.x;

    float vals[4];
    float s = 0.f, ss = 0.f;
#pragma unroll
    for (int i = 0; i < 4; i++) {
        float v = xr[tid + i * 256];
        vals[i] = v;
        s += v;
        ss += v * v;
    }
#pragma unroll
    for (int o = 16; o > 0; o >>= 1) {
        s  += __shfl_xor_sync(0xffffffffu, s, o);
        ss += __shfl_xor_sync(0xffffffffu, ss, o);
    }
    __shared__ float sbuf[8], ssbuf[8];
    int warp = tid >> 5, lane = tid & 31;
    if (lane == 0) { sbuf[warp] = s; ssbuf[warp] = ss; }
    __syncthreads();
    float ts = 0.f, tss = 0.f;
#pragma unroll
    for (int wq = 0; wq < 8; wq++) { ts += sbuf[wq]; tss += ssbuf[wq]; }
    float mu = ts * (1.0f / D_MODEL);
    float var = tss * (1.0f / D_MODEL) - mu * mu;
    float inv = rsqrtf(var + LN_EPS);
#pragma unroll
    for (int i = 0; i < 4; i++) {
        int d = tid + i * 256;
        outr[d] = tf32r((vals[i] - mu) * inv * g[d] + b[d]);
    }
}

// ---------------- weight prepack ----------------------------------------------
__global__ void pack_w(const float* __restrict__ wq, const float* __restrict__ wg,
                       float* __restrict__ wt) {
    long long idx = (long long)blockIdx.x * 256 + threadIdx.x;  // n*1024 + k
    int n = (int)(idx >> 10);
    int k = (int)(idx & 1023);
    float v = (n < 3072) ? wq[(long long)k * 3072 + n] : wg[(long long)k * 1024 + n - 3072];
    wt[idx] = tf32r(v);
}
__global__ void pack_bias(const float* __restrict__ bq, const float* __restrict__ bg,
                          float* __restrict__ bc) {
    int n = blockIdx.x * 256 + threadIdx.x;
    bc[n] = (n < 3072) ? bq[n] : bg[n - 3072];
}
__global__ void pack_wp(const float* __restrict__ wp, float* __restrict__ wpT) {
    long long idx = (long long)blockIdx.x * 256 + threadIdx.x;  // n*1024 + k
    int n = (int)(idx >> 10);
    int k = (int)(idx & 1023);
    wpT[idx] = tf32r(wp[(long long)k * 1024 + n]);
}

// ---------------- activations: q=elu(q)+1, k=elu(k*sigmoid(g))+1, round v ----
__global__ void act_kernel(float* __restrict__ qkvg) {
    long long idx = (long long)blockIdx.x * 256 + threadIdx.x;
    long long row = idx >> 10;
    int d = (int)(idx & 1023);
    float* base = qkvg + row * 4096;
    float q = base[d];
    float k = base[1024 + d];
    float v = base[2048 + d];
    float gt = base[3072 + d];
    float sg = 1.f / (1.f + expf(-gt));
    float kg = k * sg;
    q  = (q  > 0.f ? q  : expm1f(q))  + 1.f;
    kg = (kg > 0.f ? kg : expm1f(kg)) + 1.f;
    base[d] = tf32r(q);
    base[1024 + d] = tf32r(kg);
    base[2048 + d] = tf32r(v);
}

// ---------------- per-chunk K column sums ------------------------------------
__global__ void ksum_kernel(const float* __restrict__ qkvg, float* __restrict__ pk) {
    int u = blockIdx.x;
    int d = blockIdx.y * 256 + threadIdx.x;
    const float* base = qkvg + (long long)u * CHUNK * 4096 + 1024 + d;
    float s = 0.f;
#pragma unroll 8
    for (int t = 0; t < CHUNK; t++) s += base[(long long)t * 4096];
    pk[u * D_MODEL + d] = s;
}

// ---------------- exclusive prefix over chunks (in place, round stores) ------
__global__ void prefix_p(float* __restrict__ P) {
    long long e = (long long)blockIdx.x * 256 + threadIdx.x;
    int b = (int)(e >> 20);
    long long off = e & 1048575;
    float* base = P + (long long)b * NCHUNK * 1048576 + off;
    float run = 0.f;
#pragma unroll
    for (int c = 0; c < NCHUNK; c++) {
        float t = base[(long long)c * 1048576];
        base[(long long)c * 1048576] = tf32r(run);
        run += t;
    }
}

__global__ void prefix_k(float* __restrict__ Pk) {
    int e = blockIdx.x * 256 + threadIdx.x;
    int b = e >> 10;
    int d = e & 1023;
    float* base = Pk + b * NCHUNK * D_MODEL + d;
    float run = 0.f;
#pragma unroll
    for (int c = 0; c < NCHUNK; c++) {
        float t = base[c * D_MODEL];
        base[c * D_MODEL] = run;
        run += t;
    }
}

// ---------------- den (inter-chunk part): den[r] = eps + q_r . Sk[u] ---------
__global__ void den_kernel(const float* __restrict__ qkvg,
                           const float* __restrict__ pk,
                           float* __restrict__ den) {
    int warp = blockIdx.x * 8 + (threadIdx.x >> 5);
    int lane = threadIdx.x & 31;
    const float* q  = qkvg + (long long)warp * 4096;
    const float* sk = pk + (warp / CHUNK) * D_MODEL;
    float s = 0.f;
#pragma unroll 8
    for (int i = lane; i < D_MODEL; i += 32) s += q[i] * sk[i];
#pragma unroll
    for (int o = 16; o > 0; o >>= 1) s += __shfl_xor_sync(0xffffffffu, s, o);
    if (lane == 0) den[warp] = s + DEN_EPS;
}

// ---------------- launch ------------------------------------------------------
extern "C" void kernel_launch(void* const* d_in, const int* in_sizes, int n_in,
                              void* d_out, int out_size) {
    const float* x      = (const float*)d_in[0];
    const float* w_qkv  = (const float*)d_in[1];
    const float* b_qkv  = (const float*)d_in[2];
    const float* w_gate = (const float*)d_in[3];
    const float* b_gate = (const float*)d_in[4];
    const float* w_proj = (const float*)d_in[5];
    const float* b_proj = (const float*)d_in[6];
    const float* ln_g   = (const float*)d_in[7];
    const float* ln_b   = (const float*)d_in[8];
    float* out = (float*)d_out;

    float *p_xn, *p_qkvg, *p_P, *p_Pk, *p_attn, *p_num, *p_den, *p_wt, *p_wpT, *p_bcat;
    cudaGetSymbolAddress((void**)&p_xn,   g_xn);
    cudaGetSymbolAddress((void**)&p_qkvg, g_qkvg);
    cudaGetSymbolAddress((void**)&p_P,    g_P);
    cudaGetSymbolAddress((void**)&p_Pk,   g_Pk);
    cudaGetSymbolAddress((void**)&p_attn, g_attn);
    cudaGetSymbolAddress((void**)&p_num,  g_num);
    cudaGetSymbolAddress((void**)&p_den,  g_den);
    cudaGetSymbolAddress((void**)&p_wt,   g_wt);
    cudaGetSymbolAddress((void**)&p_wpT,  g_wpT);
    cudaGetSymbolAddress((void**)&p_bcat, g_bcat);

    cudaFuncSetAttribute(tgemm<0, 0, 1>, cudaFuncAttributeMaxDynamicSharedMemorySize, SMEM_BYTES);
    cudaFuncSetAttribute(tgemm<1, 1, 0>, cudaFuncAttributeMaxDynamicSharedMemorySize, SMEM_BYTES);
    cudaFuncSetAttribute(tgemm<0, 0, 0>, cudaFuncAttributeMaxDynamicSharedMemorySize, SMEM_BYTES);
    cudaFuncSetAttribute(tgemm<0, 0, 3>, cudaFuncAttributeMaxDynamicSharedMemorySize, SMEM_BYTES);
    cudaFuncSetAttribute(tgemm<0, 1, 4>, cudaFuncAttributeMaxDynamicSharedMemorySize, SMEM_BYTES);

    // 0. prepack weights (tf32 round + transpose; qkv||gate fused)
    pack_w   <<<(4096 * 1024) / 256, 256>>>(w_qkv, w_gate, p_wt);
    pack_bias<<<4096 / 256, 256>>>(b_qkv, b_gate, p_bcat);
    pack_wp  <<<(1024 * 1024) / 256, 256>>>(w_proj, p_wpT);

    // 1. LayerNorm (tf32-rounded xn)
    ln_kernel<<<NROWS, 256>>>(x, ln_g, ln_b, p_xn);

    // 2. qkvg = xn @ [w_qkv|w_gate] + bias   -> g_qkvg [16384 x 4096]
    tgemm<0, 0, 1><<<dim3(4096 / 128, NROWS / 128, 1), 256, SMEM_BYTES>>>(
        p_xn, D_MODEL, 0, p_wt, D_MODEL, 0,
        p_qkvg, 4096, 0, p_bcat, nullptr, D_MODEL);

    // 3. activations (q, gated k, rounded v)
    act_kernel<<<(NROWS * D_MODEL) / 256, 256>>>(p_qkvg);

    // 4. per-chunk K colsums
    ksum_kernel<<<dim3(NUNITS, D_MODEL / 256), 256>>>(p_qkvg, p_Pk);

    // 5. Pt_u = V_u^T @ K_u  (stored [d2][d1], batched over units)
    tgemm<1, 1, 0><<<dim3(D_MODEL / 128, D_MODEL / 128, NUNITS), 256, SMEM_BYTES>>>(
        p_qkvg + 2048, 4096, (long long)CHUNK * 4096,
        p_qkvg + 1024, 4096, (long long)CHUNK * 4096,
        p_P, D_MODEL, (long long)D_MODEL * D_MODEL,
        nullptr, nullptr, CHUNK);

    // 6. exclusive prefix scans over chunks
    prefix_p<<<(B_SZ * 1048576) / 256, 256>>>(p_P);
    prefix_k<<<(B_SZ * D_MODEL) / 256, 256>>>(p_Pk);

    // 7. den = eps + q . Sk   (must precede masked-attn atomics)
    den_kernel<<<NROWS / 8, 256>>>(p_qkvg, p_Pk, p_den);

    // 8. num = Q_u @ S_u   (B = Pt prefix, K-major direct)
    tgemm<0, 0, 0><<<dim3(D_MODEL / 128, CHUNK / 128, NUNITS), 256, SMEM_BYTES>>>(
        p_qkvg, 4096, (long long)CHUNK * 4096,
        p_P, D_MODEL, (long long)D_MODEL * D_MODEL,
        p_num, D_MODEL, (long long)CHUNK * D_MODEL,
        nullptr, nullptr, D_MODEL);

    // 9. attn_u = tril(Q_u @ K_u^T), rounded; rowsums atomically into den
    tgemm<0, 0, 3><<<dim3(CHUNK / 128, CHUNK / 128, NUNITS), 256, SMEM_BYTES>>>(
        p_qkvg, 4096, (long long)CHUNK * 4096,
        p_qkvg + 1024, 4096, (long long)CHUNK * 4096,
        p_attn, CHUNK, (long long)CHUNK * CHUNK,
        nullptr, p_den, D_MODEL);

    // 10. num = (num + attn_u @ V_u) / den   (fused divide)
    tgemm<0, 1, 4><<<dim3(D_MODEL / 128, CHUNK / 128, NUNITS), 256, SMEM_BYTES>>>(
        p_attn, CHUNK, (long long)CHUNK * CHUNK,
        p_qkvg + 2048, 4096, (long long)CHUNK * 4096,
        p_num, D_MODEL, (long long)CHUNK * D_MODEL,
        nullptr, p_den, CHUNK);

    // 11. out = num @ w_proj + b_proj
    tgemm<0, 0, 1><<<dim3(D_MODEL / 128, NROWS / 128, 1), 256, SMEM_BYTES>>>(
        p_num, D_MODEL, 0, p_wpT, D_MODEL, 0,
        out, D_MODEL, 0, b_proj, nullptr, D_MODEL);
}

// round 5
// speedup vs baseline: 6.4954x; 2.1261x over previous
#include <cuda_runtime.h>
#include <cuda_fp16.h>
#include <cstdint>
#include <math.h>

#define D_MODEL 1024
#define B_SZ 4
#define T_SZ 4096
#define NROWS (B_SZ * T_SZ)          /* 16384 */
#define CHUNK 256
#define NCHUNK (T_SZ / CHUNK)        /* 16 */
#define NUNITS (B_SZ * NCHUNK)       /* 64 */
#define LN_EPS 1e-5f
#define DEN_EPS 1e-6f

// ---------------- scratch (device globals; no allocations allowed) -----------
__device__ __half g_xnh[(size_t)NROWS * D_MODEL];                  // 32 MB
__device__ __half g_qkvh[(size_t)NROWS * 4 * D_MODEL];             // 128 MB q|k|v|gate
__device__ __half g_kT[(size_t)B_SZ * D_MODEL * T_SZ];             // 32 MB  [b][d][t]
__device__ __half g_vT[(size_t)B_SZ * D_MODEL * T_SZ];             // 32 MB
__device__ __half g_Ph[(size_t)NUNITS * D_MODEL * D_MODEL];        // 128 MB Pt=V^T K -> excl prefix
__device__ float  g_Pk[NUNITS * D_MODEL];
__device__ __half g_attnh[(size_t)NUNITS * CHUNK * CHUNK];         // 8 MB
__device__ float  g_num[(size_t)NROWS * D_MODEL];                  // 64 MB
__device__ __half g_numh[(size_t)NROWS * D_MODEL];                 // 32 MB
__device__ float  g_den[NROWS];
__device__ __half g_wth[(size_t)4096 * 1024];                      // qkv|gate weights [n][k]
__device__ __half g_wph[(size_t)1024 * 1024];                      // w_proj^T [n][k]
__device__ float  g_bcat[4096];

// ---------------- helpers -----------------------------------------------------
__device__ __forceinline__ uint32_t smem_u32(const void* p) {
    uint32_t a;
    asm("{ .reg .u64 t; cvta.to.shared.u64 t, %1; cvt.u32.u64 %0, t; }" : "=r"(a) : "l"(p));
    return a;
}

#define CP16(dst, src) \
    asm volatile("cp.async.cg.shared.global [%0], [%1], 16;" :: "r"(dst), "l"(src))
#define CP_COMMIT() asm volatile("cp.async.commit_group;" ::: "memory")
#define CP_WAIT(n)  asm volatile("cp.async.wait_group %0;" :: "n"(n) : "memory")

#define LDM4(r0, r1, r2, r3, addr) \
    asm volatile("ldmatrix.sync.aligned.m8n8.x4.shared.b16 {%0,%1,%2,%3}, [%4];" \
                 : "=r"(r0), "=r"(r1), "=r"(r2), "=r"(r3) : "r"(addr))

#define MMA16(c, a, b) \
    asm volatile( \
        "mma.sync.aligned.m16n8k16.row.col.f32.f16.f16.f32 " \
        "{%0,%1,%2,%3}, {%4,%5,%6,%7}, {%8,%9}, {%0,%1,%2,%3};" \
        : "+f"((c)[0]), "+f"((c)[1]), "+f"((c)[2]), "+f"((c)[3]) \
        : "r"((a)[0]), "r"((a)[1]), "r"((a)[2]), "r"((a)[3]), \
          "r"((b)[0]), "r"((b)[1]))

// ---------------- fp16 tensor-core GEMM ---------------------------------------
// Tile 128x128, 8 warps (2M x 4N), warp tile 64x32, mma m16n8k16.
// K-tile 64, 3-stage cp.async, ldmatrix frags, swizzled smem (128B rows of 64 halves).
// EPI: 0 f32 out, 1 bias+f32 out, 2 half out, 3 mask+half out+rowsum->den,
//      4 (Cin + acc)*rcp(den) -> half out (Keff = m0+128), 5 bias+half out.
#define STB 32768                   /* stage bytes: A 16KB + B 16KB */
#define SMEM_BYTES (3 * STB)        /* 98304 */

template <int EPI>
__global__ void __launch_bounds__(256, 2) hgemm(
    const __half* __restrict__ A, int lda, long long sAb, long long sAc,
    const __half* __restrict__ B, int ldb, long long sBb, long long sBc,
    void* __restrict__ C, int ldc, long long sC,
    const float* __restrict__ Cin, long long sCin,
    const float* __restrict__ bias, float* __restrict__ den, int K) {
    extern __shared__ char sm[];
    const uint32_t su = smem_u32(sm);
    const int tid = threadIdx.x;
    const int u = blockIdx.z;
    const int ub = u >> 4, uc = u & 15;
    const __half* Ab = A + ub * sAb + uc * sAc;
    const __half* Bb = B + ub * sBb + uc * sBc;
    const int m0 = blockIdx.y * 128;
    const int n0 = blockIdx.x * 128;

    if (EPI == 3 && n0 >= m0 + 128) {  // fully masked block: zero-fill, done
        __half* Ch = (__half*)C + (long long)u * sC;
        uint4 z = make_uint4(0, 0, 0, 0);
#pragma unroll
        for (int p = 0; p < 8; p++) {
            int id = tid + p * 256;
            int row = id >> 4, q = id & 15;
            *reinterpret_cast<uint4*>(Ch + (long long)(m0 + row) * ldc + n0 + q * 8) = z;
        }
        return;
    }

    int Keff = K;
    if (EPI == 4) Keff = (K < m0 + 128) ? K : (m0 + 128);

    const int lane = tid & 31;
    const int w = tid >> 5;
    const int wm = (w & 1) * 64;
    const int wn = (w >> 1) * 32;
    const int g = lane >> 3;
    const int lr = lane & 7;
    const int l4q = lane >> 2;
    const int lmq = lane & 3;

    // ldmatrix row byte-offsets (row stride 128B within tile)
    int rA[4], rB[2];
#pragma unroll
    for (int mt = 0; mt < 4; mt++) rA[mt] = (wm + mt * 16 + lr + 8 * (g & 1)) * 128;
#pragma unroll
    for (int p = 0; p < 2; p++) rB[p] = (wn + p * 16 + lr + 8 * (g >> 1)) * 128;
    const int cxA = (g >> 1);   // chunk adders
    const int cxB = (g & 1);

    auto loadA = [&](int st, int kt) {
        uint32_t dst = su + st * STB;
        int k0 = kt * 64;
#pragma unroll
        for (int p = 0; p < 4; p++) {
            int c = tid + p * 256;
            int row = c >> 3, ch = c & 7;
            const __half* src = Ab + (long long)(m0 + row) * lda + k0 + ch * 8;
            CP16(dst + row * 128 + ((ch ^ (row & 7)) << 4), src);
        }
    };
    auto loadB = [&](int st, int kt) {
        uint32_t dst = su + st * STB + 16384;
        int k0 = kt * 64;
#pragma unroll
        for (int p = 0; p < 4; p++) {
            int c = tid + p * 256;
            int row = c >> 3, ch = c & 7;
            const __half* src = Bb + (long long)(n0 + row) * ldb + k0 + ch * 8;
            CP16(dst + row * 128 + ((ch ^ (row & 7)) << 4), src);
        }
    };

    float acc[4][4][4];
#pragma unroll
    for (int mt = 0; mt < 4; mt++)
#pragma unroll
        for (int nt = 0; nt < 4; nt++)
#pragma unroll
            for (int r = 0; r < 4; r++) acc[mt][nt][r] = 0.f;

    const int KT = Keff >> 6;
    loadA(0, 0); loadB(0, 0); CP_COMMIT();
    if (KT > 1) { loadA(1, 1); loadB(1, 1); CP_COMMIT(); }

    int st = 0, stn = 2;
    for (int i = 0; i < KT; i++) {
        if (i < KT - 1) { CP_WAIT(1); } else { CP_WAIT(0); }
        __syncthreads();
        if (i + 2 < KT) {
            loadA(stn, i + 2); loadB(stn, i + 2); CP_COMMIT();
            stn = (stn == 2) ? 0 : stn + 1;
        }
        uint32_t Abase = su + st * STB;
        uint32_t Bbase = Abase + 16384;
        st = (st == 2) ? 0 : st + 1;
#pragma unroll
        for (int kk = 0; kk < 4; kk++) {
            uint32_t af[4][4], bf[4][2];
            int cA = ((kk * 2 + cxA) ^ lr) << 4;
            int cB = ((kk * 2 + cxB) ^ lr) << 4;
#pragma unroll
            for (int mt = 0; mt < 4; mt++)
                LDM4(af[mt][0], af[mt][1], af[mt][2], af[mt][3], Abase + rA[mt] + cA);
            LDM4(bf[0][0], bf[0][1], bf[1][0], bf[1][1], Bbase + rB[0] + cB);
            LDM4(bf[2][0], bf[2][1], bf[3][0], bf[3][1], Bbase + rB[1] + cB);
#pragma unroll
            for (int mt = 0; mt < 4; mt++)
#pragma unroll
                for (int nt = 0; nt < 4; nt++)
                    MMA16(acc[mt][nt], af[mt], bf[nt]);
        }
        // no trailing sync needed: next iteration's CP_WAIT+sync guards reuse
        __syncthreads();
    }

    // ---- epilogue ----
    float* Cf = (float*)C + (long long)u * sC;
    __half* Ch = (__half*)C + (long long)u * sC;
    const float* Ci = Cin ? Cin + (long long)u * sCin : nullptr;

#pragma unroll
    for (int mt = 0; mt < 4; mt++) {
        int row0 = m0 + wm + mt * 16 + l4q;
        int row1 = row0 + 8;
        float rs0 = 0.f, rs1 = 0.f, rcp0 = 0.f, rcp1 = 0.f;
        if (EPI == 4) {
            rcp0 = __frcp_rn(den[(long long)u * CHUNK + row0]);
            rcp1 = __frcp_rn(den[(long long)u * CHUNK + row1]);
        }
#pragma unroll
        for (int nt = 0; nt < 4; nt++) {
            int col = n0 + wn + nt * 8 + lmq * 2;
            float v0 = acc[mt][nt][0], v1 = acc[mt][nt][1];
            float v2 = acc[mt][nt][2], v3 = acc[mt][nt][3];
            if (EPI == 1 || EPI == 5) {
                float b0 = bias[col], b1 = bias[col + 1];
                v0 += b0; v1 += b1; v2 += b0; v3 += b1;
            }
            if (EPI == 4) {
                const float* q0 = Ci + (long long)row0 * ldc + col;
                const float* q1 = Ci + (long long)row1 * ldc + col;
                v0 = (v0 + q0[0]) * rcp0; v1 = (v1 + q0[1]) * rcp0;
                v2 = (v2 + q1[0]) * rcp1; v3 = (v3 + q1[1]) * rcp1;
            }
            if (EPI == 3) {
                v0 = (col     > row0) ? 0.f : v0;
                v1 = (col + 1 > row0) ? 0.f : v1;
                v2 = (col     > row1) ? 0.f : v2;
                v3 = (col + 1 > row1) ? 0.f : v3;
            }
            if (EPI == 0 || EPI == 1) {
                *reinterpret_cast<float2*>(Cf + (long long)row0 * ldc + col) = make_float2(v0, v1);
                *reinterpret_cast<float2*>(Cf + (long long)row1 * ldc + col) = make_float2(v2, v3);
            } else {
                __half2 h0 = __floats2half2_rn(v0, v1);
                __half2 h1 = __floats2half2_rn(v2, v3);
                if (EPI == 3) {  // rowsum of the rounded values for num/den consistency
                    rs0 += __half2float(h0.x) + __half2float(h0.y);
                    rs1 += __half2float(h1.x) + __half2float(h1.y);
                }
                *reinterpret_cast<__half2*>(Ch + (long long)row0 * ldc + col) = h0;
                *reinterpret_cast<__half2*>(Ch + (long long)row1 * ldc + col) = h1;
            }
        }
        if (EPI == 3) {
            rs0 += __shfl_xor_sync(0xffffffffu, rs0, 1);
            rs0 += __shfl_xor_sync(0xffffffffu, rs0, 2);
            rs1 += __shfl_xor_sync(0xffffffffu, rs1, 1);
            rs1 += __shfl_xor_sync(0xffffffffu, rs1, 2);
            if (lmq == 0) {
                atomicAdd(den + (long long)u * CHUNK + row0, rs0);
                atomicAdd(den + (long long)u * CHUNK + row1, rs1);
            }
        }
    }
}

// ---------------- LayerNorm -> fp16 -------------------------------------------
__global__ void ln_kernel(const float* __restrict__ x,
                          const float* __restrict__ g,
                          const float* __restrict__ b,
                          __half* __restrict__ xn) {
    int row = blockIdx.x;
    const float* xr = x + (size_t)row * D_MODEL;
    __half* outr = xn + (size_t)row * D_MODEL;
    int tid = threadIdx.x;
    float vals[4];
    float s = 0.f, ss = 0.f;
#pragma unroll
    for (int i = 0; i < 4; i++) {
        float v = xr[tid + i * 256];
        vals[i] = v; s += v; ss += v * v;
    }
#pragma unroll
    for (int o = 16; o > 0; o >>= 1) {
        s  += __shfl_xor_sync(0xffffffffu, s, o);
        ss += __shfl_xor_sync(0xffffffffu, ss, o);
    }
    __shared__ float sbuf[8], ssbuf[8];
    int warp = tid >> 5, lane = tid & 31;
    if (lane == 0) { sbuf[warp] = s; ssbuf[warp] = ss; }
    __syncthreads();
    float ts = 0.f, tss = 0.f;
#pragma unroll
    for (int wq = 0; wq < 8; wq++) { ts += sbuf[wq]; tss += ssbuf[wq]; }
    float mu = ts * (1.0f / D_MODEL);
    float var = tss * (1.0f / D_MODEL) - mu * mu;
    float inv = rsqrtf(var + LN_EPS);
#pragma unroll
    for (int i = 0; i < 4; i++) {
        int d = tid + i * 256;
        outr[d] = __float2half_rn((vals[i] - mu) * inv * g[d] + b[d]);
    }
}

// ---------------- weight prepack (fp16, transposed) ---------------------------
__global__ void pack_w(const float* __restrict__ wq, const float* __restrict__ wg,
                       __half* __restrict__ wt) {
    long long idx = (long long)blockIdx.x * 256 + threadIdx.x;  // n*1024 + k
    int n = (int)(idx >> 10);
    int k = (int)(idx & 1023);
    float v = (n < 3072) ? wq[(long long)k * 3072 + n] : wg[(long long)k * 1024 + n - 3072];
    wt[idx] = __float2half_rn(v);
}
__global__ void pack_bias(const float* __restrict__ bq, const float* __restrict__ bg,
                          float* __restrict__ bc) {
    int n = blockIdx.x * 256 + threadIdx.x;
    bc[n] = (n < 3072) ? bq[n] : bg[n - 3072];
}
__global__ void pack_wp(const float* __restrict__ wp, __half* __restrict__ wpT) {
    long long idx = (long long)blockIdx.x * 256 + threadIdx.x;
    int n = (int)(idx >> 10);
    int k = (int)(idx & 1023);
    wpT[idx] = __float2half_rn(wp[(long long)k * 1024 + n]);
}

// ---------------- activations (in place on qkvh) ------------------------------
__global__ void act_kernel(__half* __restrict__ qkvh) {
    long long idx = (long long)blockIdx.x * 256 + threadIdx.x;
    long long row = idx >> 10;
    int d = (int)(idx & 1023);
    __half* base = qkvh + row * 4096;
    float q  = __half2float(base[d]);
    float k  = __half2float(base[1024 + d]);
    float gt = __half2float(base[3072 + d]);
    float sg = 1.f / (1.f + expf(-gt));
    float kg = k * sg;
    q  = (q  > 0.f ? q  : expm1f(q))  + 1.f;
    kg = (kg > 0.f ? kg : expm1f(kg)) + 1.f;
    base[d] = __float2half_rn(q);
    base[1024 + d] = __float2half_rn(kg);
}

// ---------------- k,v transpose to [b][d][t] ----------------------------------
__global__ void transpose_kv(const __half* __restrict__ qkvh,
                             __half* __restrict__ kT, __half* __restrict__ vT) {
    __shared__ __half sk[32][34], sv[32][34];
    int tx = threadIdx.x, ty = threadIdx.y;
    int t0 = blockIdx.x * 32, d0 = blockIdx.y * 32;
#pragma unroll
    for (int i = 0; i < 4; i++) {
        long long r = t0 + ty + i * 8;
        sk[ty + i * 8][tx] = qkvh[r * 4096 + 1024 + d0 + tx];
        sv[ty + i * 8][tx] = qkvh[r * 4096 + 2048 + d0 + tx];
    }
    __syncthreads();
    int tg = t0 + tx;
    int b = tg >> 12, t = tg & 4095;
#pragma unroll
    for (int i = 0; i < 4; i++) {
        int d = d0 + ty + i * 8;
        long long o = ((long long)b * 1024 + d) * 4096 + t;
        kT[o] = sk[tx][ty + i * 8];
        vT[o] = sv[tx][ty + i * 8];
    }
}

// ---------------- per-chunk K column sums ------------------------------------
__global__ void ksum_kernel(const __half* __restrict__ qkvh, float* __restrict__ pk) {
    int u = blockIdx.x;
    int d = blockIdx.y * 256 + threadIdx.x;
    const __half* base = qkvh + (long long)u * CHUNK * 4096 + 1024 + d;
    float s = 0.f;
#pragma unroll 8
    for (int t = 0; t < CHUNK; t++) s += __half2float(base[(long long)t * 4096]);
    pk[u * D_MODEL + d] = s;
}

// ---------------- exclusive prefix over chunks --------------------------------
__global__ void prefix_p(__half* __restrict__ P) {
    long long e = (long long)blockIdx.x * 256 + threadIdx.x;
    int b = (int)(e >> 20);
    long long off = e & 1048575;
    __half* base = P + (long long)b * NCHUNK * 1048576 + off;
    float run = 0.f;
#pragma unroll
    for (int c = 0; c < NCHUNK; c++) {
        float t = __half2float(base[(long long)c * 1048576]);
        base[(long long)c * 1048576] = __float2half_rn(run);
        run += t;
    }
}

__global__ void prefix_k(float* __restrict__ Pk) {
    int e = blockIdx.x * 256 + threadIdx.x;
    int b = e >> 10;
    int d = e & 1023;
    float* base = Pk + b * NCHUNK * D_MODEL + d;
    float run = 0.f;
#pragma unroll
    for (int c = 0; c < NCHUNK; c++) {
        float t = base[c * D_MODEL];
        base[c * D_MODEL] = run;
        run += t;
    }
}

// ---------------- den = eps + q . Sk ------------------------------------------
__global__ void den_kernel(const __half* __restrict__ qkvh,
                           const float* __restrict__ pk,
                           float* __restrict__ den) {
    int warp = blockIdx.x * 8 + (threadIdx.x >> 5);
    int lane = threadIdx.x & 31;
    const __half* q = qkvh + (long long)warp * 4096;
    const float* sk = pk + (warp / CHUNK) * D_MODEL;
    float s = 0.f;
#pragma unroll 8
    for (int i = lane; i < D_MODEL; i += 32) s += __half2float(q[i]) * sk[i];
#pragma unroll
    for (int o = 16; o > 0; o >>= 1) s += __shfl_xor_sync(0xffffffffu, s, o);
    if (lane == 0) den[warp] = s + DEN_EPS;
}

// ---------------- launch ------------------------------------------------------
extern "C" void kernel_launch(void* const* d_in, const int* in_sizes, int n_in,
                              void* d_out, int out_size) {
    const float* x      = (const float*)d_in[0];
    const float* w_qkv  = (const float*)d_in[1];
    const float* b_qkv  = (const float*)d_in[2];
    const float* w_gate = (const float*)d_in[3];
    const float* b_gate = (const float*)d_in[4];
    const float* w_proj = (const float*)d_in[5];
    const float* b_proj = (const float*)d_in[6];
    const float* ln_g   = (const float*)d_in[7];
    const float* ln_b   = (const float*)d_in[8];
    float* out = (float*)d_out;

    __half *p_xnh, *p_qkvh, *p_kT, *p_vT, *p_Ph, *p_attnh, *p_numh, *p_wth, *p_wph;
    float *p_Pk, *p_num, *p_den, *p_bcat;
    cudaGetSymbolAddress((void**)&p_xnh,   g_xnh);
    cudaGetSymbolAddress((void**)&p_qkvh,  g_qkvh);
    cudaGetSymbolAddress((void**)&p_kT,    g_kT);
    cudaGetSymbolAddress((void**)&p_vT,    g_vT);
    cudaGetSymbolAddress((void**)&p_Ph,    g_Ph);
    cudaGetSymbolAddress((void**)&p_Pk,    g_Pk);
    cudaGetSymbolAddress((void**)&p_attnh, g_attnh);
    cudaGetSymbolAddress((void**)&p_num,   g_num);
    cudaGetSymbolAddress((void**)&p_numh,  g_numh);
    cudaGetSymbolAddress((void**)&p_den,   g_den);
    cudaGetSymbolAddress((void**)&p_wth,   g_wth);
    cudaGetSymbolAddress((void**)&p_wph,   g_wph);
    cudaGetSymbolAddress((void**)&p_bcat,  g_bcat);

    cudaFuncSetAttribute(hgemm<0>, cudaFuncAttributeMaxDynamicSharedMemorySize, SMEM_BYTES);
    cudaFuncSetAttribute(hgemm<1>, cudaFuncAttributeMaxDynamicSharedMemorySize, SMEM_BYTES);
    cudaFuncSetAttribute(hgemm<2>, cudaFuncAttributeMaxDynamicSharedMemorySize, SMEM_BYTES);
    cudaFuncSetAttribute(hgemm<3>, cudaFuncAttributeMaxDynamicSharedMemorySize, SMEM_BYTES);
    cudaFuncSetAttribute(hgemm<4>, cudaFuncAttributeMaxDynamicSharedMemorySize, SMEM_BYTES);
    cudaFuncSetAttribute(hgemm<5>, cudaFuncAttributeMaxDynamicSharedMemorySize, SMEM_BYTES);

#define UNI(s) 16LL * (s), (long long)(s)

    // 0. prepack
    pack_w   <<<(4096 * 1024) / 256, 256>>>(w_qkv, w_gate, p_wth);
    pack_bias<<<4096 / 256, 256>>>(b_qkv, b_gate, p_bcat);
    pack_wp  <<<(1024 * 1024) / 256, 256>>>(w_proj, p_wph);

    // 1. LayerNorm -> fp16
    ln_kernel<<<NROWS, 256>>>(x, ln_g, ln_b, p_xnh);

    // 2. qkvg = xn @ [w_qkv|w_gate] + bias  -> qkvh fp16
    hgemm<5><<<dim3(32, 128, 1), 256, SMEM_BYTES>>>(
        p_xnh, 1024, UNI(0), p_wth, 1024, UNI(0),
        p_qkvh, 4096, 0, nullptr, 0, p_bcat, nullptr, 1024);

    // 3. activations in place
    act_kernel<<<(NROWS * D_MODEL) / 256, 256>>>(p_qkvh);

    // 4. transpose k,v -> [b][d][t]
    transpose_kv<<<dim3(NROWS / 32, D_MODEL / 32), dim3(32, 8)>>>(p_qkvh, p_kT, p_vT);

    // 5. per-chunk K colsums
    ksum_kernel<<<dim3(NUNITS, D_MODEL / 256), 256>>>(p_qkvh, p_Pk);

    // 6. Pt_u = V_u^T @ K_u -> Ph fp16
    hgemm<2><<<dim3(8, 8, NUNITS), 256, SMEM_BYTES>>>(
        p_vT, 4096, 4194304LL, 256LL, p_kT, 4096, 4194304LL, 256LL,
        p_Ph, 1024, 1048576LL, nullptr, 0, nullptr, nullptr, 256);

    // 7. exclusive prefix scans
    prefix_p<<<(B_SZ * 1048576) / 256, 256>>>(p_Ph);
    prefix_k<<<(B_SZ * D_MODEL) / 256, 256>>>(p_Pk);

    // 8. den = eps + q . Sk  (before attn atomics)
    den_kernel<<<NROWS / 8, 256>>>(p_qkvh, p_Pk, p_den);

    // 9. num = Q_u @ S_u -> fp32
    hgemm<0><<<dim3(8, 2, NUNITS), 256, SMEM_BYTES>>>(
        p_qkvh, 4096, UNI(1048576LL), p_Ph, 1024, UNI(1048576LL),
        p_num, 1024, 262144LL, nullptr, 0, nullptr, nullptr, 1024);

    // 10. attn = tril(Q_u @ K_u^T) -> fp16, rowsums -> den
    hgemm<3><<<dim3(2, 2, NUNITS), 256, SMEM_BYTES>>>(
        p_qkvh, 4096, UNI(1048576LL), p_qkvh + 1024, 4096, UNI(1048576LL),
        p_attnh, 256, 65536LL, nullptr, 0, nullptr, p_den, 1024);

    // 11. numh = (num + attn @ V_u) / den  -> fp16 (Keff causal-truncated)
    hgemm<4><<<dim3(8, 2, NUNITS), 256, SMEM_BYTES>>>(
        p_attnh, 256, UNI(65536LL), p_vT, 4096, 4194304LL, 256LL,
        p_numh, 1024, 262144LL, p_num, 262144LL, nullptr, p_den, 256);

    // 12. out = numh @ w_proj + b_proj
    hgemm<1><<<dim3(8, 128, 1), 256, SMEM_BYTES>>>(
        p_numh, 1024, UNI(0), p_wph, 1024, UNI(0),
        out, 1024, 0, nullptr, 0, b_proj, nullptr, 1024);
}

// round 6
// speedup vs baseline: 6.9539x; 1.0706x over previous
#include <cuda_runtime.h>
#include <cuda_fp16.h>
#include <cstdint>
#include <math.h>

#define D_MODEL 1024
#define B_SZ 4
#define T_SZ 4096
#define NROWS (B_SZ * T_SZ)          /* 16384 */
#define CHUNK 256
#define NCHUNK (T_SZ / CHUNK)        /* 16 */
#define NUNITS (B_SZ * NCHUNK)       /* 64 */
#define LN_EPS 1e-5f
#define DEN_EPS 1e-6f

// ---------------- scratch (device globals; no allocations allowed) -----------
__device__ __half g_xnh[(size_t)NROWS * D_MODEL];                  // 32 MB
__device__ __half g_qkvh[(size_t)NROWS * 4 * D_MODEL];             // 128 MB q|k|v|gate
__device__ __half g_kT[(size_t)B_SZ * D_MODEL * T_SZ];             // 32 MB [b][d][t]
__device__ __half g_vT[(size_t)B_SZ * D_MODEL * T_SZ];             // 32 MB
__device__ __half g_Ph[(size_t)NUNITS * D_MODEL * D_MODEL];        // 128 MB Pt=V^T K -> excl prefix
__device__ float  g_Pk[NUNITS * D_MODEL];
__device__ __half g_attnh[(size_t)NUNITS * CHUNK * CHUNK];         // 8 MB
__device__ __half g_numh[(size_t)NROWS * D_MODEL];                 // 32 MB
__device__ float  g_den[NROWS];
__device__ __half g_wth[(size_t)4096 * 1024];                      // qkv|gate weights [n][k]
__device__ __half g_wph[(size_t)1024 * 1024];                      // w_proj^T [n][k]
__device__ float  g_bcat[4096];

// ---------------- helpers -----------------------------------------------------
__device__ __forceinline__ uint32_t smem_u32(const void* p) {
    uint32_t a;
    asm("{ .reg .u64 t; cvta.to.shared.u64 t, %1; cvt.u32.u64 %0, t; }" : "=r"(a) : "l"(p));
    return a;
}

#define CP16(dst, src) \
    asm volatile("cp.async.cg.shared.global [%0], [%1], 16;" :: "r"(dst), "l"(src))
#define CP_COMMIT() asm volatile("cp.async.commit_group;" ::: "memory")
#define CP_WAIT(n)  asm volatile("cp.async.wait_group %0;" :: "n"(n) : "memory")

#define LDM4(r0, r1, r2, r3, addr) \
    asm volatile("ldmatrix.sync.aligned.m8n8.x4.shared.b16 {%0,%1,%2,%3}, [%4];" \
                 : "=r"(r0), "=r"(r1), "=r"(r2), "=r"(r3) : "r"(addr))

#define MMA16(c, a, b) \
    asm volatile( \
        "mma.sync.aligned.m16n8k16.row.col.f32.f16.f16.f32 " \
        "{%0,%1,%2,%3}, {%4,%5,%6,%7}, {%8,%9}, {%0,%1,%2,%3};" \
        : "+f"((c)[0]), "+f"((c)[1]), "+f"((c)[2]), "+f"((c)[3]) \
        : "r"((a)[0]), "r"((a)[1]), "r"((a)[2]), "r"((a)[3]), \
          "r"((b)[0]), "r"((b)[1]))

#define STB 32768                   /* stage bytes: A 16KB + B 16KB */
#define SMEM_BYTES (3 * STB)        /* 98304 */

// Common warp/fragment indexing for the 128x128 tile, 8 warps (2M x 4N)
struct TileIdx {
    int lane, w, wm, wn, g, lr, l4q, lmq, cxA, cxB;
    int rA[4], rB[2];
    __device__ __forceinline__ TileIdx(int tid) {
        lane = tid & 31; w = tid >> 5;
        wm = (w & 1) * 64; wn = (w >> 1) * 32;
        g = lane >> 3; lr = lane & 7;
        l4q = lane >> 2; lmq = lane & 3;
        cxA = (g >> 1); cxB = (g & 1);
#pragma unroll
        for (int mt = 0; mt < 4; mt++) rA[mt] = (wm + mt * 16 + lr + 8 * (g & 1)) * 128;
#pragma unroll
        for (int p = 0; p < 2; p++) rB[p] = (wn + p * 16 + lr + 8 * (g >> 1)) * 128;
    }
};

// ---------------- fp16 tensor-core GEMM ---------------------------------------
// EPI: 1 bias+f32 out, 2 half out, 3 mask+half out+rowsum->den (early-exit on
//      fully masked blocks, no fill), 5 bias+half out.
template <int EPI>
__global__ void __launch_bounds__(256, 2) hgemm(
    const __half* __restrict__ A, int lda, long long sAb, long long sAc,
    const __half* __restrict__ B, int ldb, long long sBb, long long sBc,
    void* __restrict__ C, int ldc, long long sC,
    const float* __restrict__ bias, float* __restrict__ den, int K) {
    extern __shared__ char sm[];
    const uint32_t su = smem_u32(sm);
    const int tid = threadIdx.x;
    const int u = blockIdx.z;
    const int ub = u >> 4, uc = u & 15;
    const __half* Ab = A + ub * sAb + uc * sAc;
    const __half* Bb = B + ub * sBb + uc * sBc;
    const int m0 = blockIdx.y * 128;
    const int n0 = blockIdx.x * 128;

    if (EPI == 3 && n0 >= m0 + 128) return;  // fully masked: never read downstream

    const TileIdx ti(tid);

    auto loadA = [&](int st, int kt) {
        uint32_t dst = su + st * STB;
        int k0 = kt * 64;
#pragma unroll
        for (int p = 0; p < 4; p++) {
            int c = tid + p * 256;
            int row = c >> 3, ch = c & 7;
            const __half* src = Ab + (long long)(m0 + row) * lda + k0 + ch * 8;
            CP16(dst + row * 128 + ((ch ^ (row & 7)) << 4), src);
        }
    };
    auto loadB = [&](int st, int kt) {
        uint32_t dst = su + st * STB + 16384;
        int k0 = kt * 64;
#pragma unroll
        for (int p = 0; p < 4; p++) {
            int c = tid + p * 256;
            int row = c >> 3, ch = c & 7;
            const __half* src = Bb + (long long)(n0 + row) * ldb + k0 + ch * 8;
            CP16(dst + row * 128 + ((ch ^ (row & 7)) << 4), src);
        }
    };

    float acc[4][4][4];
#pragma unroll
    for (int mt = 0; mt < 4; mt++)
#pragma unroll
        for (int nt = 0; nt < 4; nt++)
#pragma unroll
            for (int r = 0; r < 4; r++) acc[mt][nt][r] = 0.f;

    const int KT = K >> 6;
    loadA(0, 0); loadB(0, 0); CP_COMMIT();
    if (KT > 1) { loadA(1, 1); loadB(1, 1); CP_COMMIT(); }

    int st = 0, stn = 2;
    for (int i = 0; i < KT; i++) {
        if (i < KT - 1) { CP_WAIT(1); } else { CP_WAIT(0); }
        __syncthreads();
        if (i + 2 < KT) {
            loadA(stn, i + 2); loadB(stn, i + 2); CP_COMMIT();
            stn = (stn == 2) ? 0 : stn + 1;
        }
        uint32_t Abase = su + st * STB;
        uint32_t Bbase = Abase + 16384;
        st = (st == 2) ? 0 : st + 1;
#pragma unroll
        for (int kk = 0; kk < 4; kk++) {
            uint32_t af[4][4], bf[4][2];
            int cA = ((kk * 2 + ti.cxA) ^ ti.lr) << 4;
            int cB = ((kk * 2 + ti.cxB) ^ ti.lr) << 4;
#pragma unroll
            for (int mt = 0; mt < 4; mt++)
                LDM4(af[mt][0], af[mt][1], af[mt][2], af[mt][3], Abase + ti.rA[mt] + cA);
            LDM4(bf[0][0], bf[0][1], bf[1][0], bf[1][1], Bbase + ti.rB[0] + cB);
            LDM4(bf[2][0], bf[2][1], bf[3][0], bf[3][1], Bbase + ti.rB[1] + cB);
#pragma unroll
            for (int mt = 0; mt < 4; mt++)
#pragma unroll
                for (int nt = 0; nt < 4; nt++)
                    MMA16(acc[mt][nt], af[mt], bf[nt]);
        }
        __syncthreads();
    }

    // ---- epilogue ----
    float* Cf = (float*)C + (long long)u * sC;
    __half* Ch = (__half*)C + (long long)u * sC;

#pragma unroll
    for (int mt = 0; mt < 4; mt++) {
        int row0 = m0 + ti.wm + mt * 16 + ti.l4q;
        int row1 = row0 + 8;
        float rs0 = 0.f, rs1 = 0.f;
#pragma unroll
        for (int nt = 0; nt < 4; nt++) {
            int col = n0 + ti.wn + nt * 8 + ti.lmq * 2;
            float v0 = acc[mt][nt][0], v1 = acc[mt][nt][1];
            float v2 = acc[mt][nt][2], v3 = acc[mt][nt][3];
            if (EPI == 1 || EPI == 5) {
                float b0 = bias[col], b1 = bias[col + 1];
                v0 += b0; v1 += b1; v2 += b0; v3 += b1;
            }
            if (EPI == 3) {
                v0 = (col     > row0) ? 0.f : v0;
                v1 = (col + 1 > row0) ? 0.f : v1;
                v2 = (col     > row1) ? 0.f : v2;
                v3 = (col + 1 > row1) ? 0.f : v3;
            }
            if (EPI == 1) {
                *reinterpret_cast<float2*>(Cf + (long long)row0 * ldc + col) = make_float2(v0, v1);
                *reinterpret_cast<float2*>(Cf + (long long)row1 * ldc + col) = make_float2(v2, v3);
            } else {
                __half2 h0 = __floats2half2_rn(v0, v1);
                __half2 h1 = __floats2half2_rn(v2, v3);
                if (EPI == 3) {
                    rs0 += __half2float(h0.x) + __half2float(h0.y);
                    rs1 += __half2float(h1.x) + __half2float(h1.y);
                }
                *reinterpret_cast<__half2*>(Ch + (long long)row0 * ldc + col) = h0;
                *reinterpret_cast<__half2*>(Ch + (long long)row1 * ldc + col) = h1;
            }
        }
        if (EPI == 3) {
            rs0 += __shfl_xor_sync(0xffffffffu, rs0, 1);
            rs0 += __shfl_xor_sync(0xffffffffu, rs0, 2);
            rs1 += __shfl_xor_sync(0xffffffffu, rs1, 1);
            rs1 += __shfl_xor_sync(0xffffffffu, rs1, 2);
            if (ti.lmq == 0) {
                atomicAdd(den + (long long)u * CHUNK + row0, rs0);
                atomicAdd(den + (long long)u * CHUNK + row1, rs1);
            }
        }
    }
}

// ---------------- fused num kernel: num = (Q@S + attn@V) / den -> fp16 --------
// Phase 1: A = q (K=1024), B = S (Ph). Phase 2: A = attn (K=Keff), B = vT.
__global__ void __launch_bounds__(256, 2) num_kernel(
    const __half* __restrict__ qkvh, const __half* __restrict__ Ph,
    const __half* __restrict__ attnh, const __half* __restrict__ vT,
    const float* __restrict__ den, __half* __restrict__ numh) {
    extern __shared__ char sm[];
    const uint32_t su = smem_u32(sm);
    const int tid = threadIdx.x;
    const int u = blockIdx.z;
    const int ub = u >> 4, uc = u & 15;
    const int m0 = blockIdx.y * 128;
    const int n0 = blockIdx.x * 128;
    const TileIdx ti(tid);

    float acc[4][4][4];
#pragma unroll
    for (int mt = 0; mt < 4; mt++)
#pragma unroll
        for (int nt = 0; nt < 4; nt++)
#pragma unroll
            for (int r = 0; r < 4; r++) acc[mt][nt][r] = 0.f;

    auto phase = [&](const __half* Ab, int lda, const __half* Bb, int ldb, int KT) {
        auto loadA = [&](int st, int kt) {
            uint32_t dst = su + st * STB;
            int k0 = kt * 64;
#pragma unroll
            for (int p = 0; p < 4; p++) {
                int c = tid + p * 256;
                int row = c >> 3, ch = c & 7;
                const __half* src = Ab + (long long)(m0 + row) * lda + k0 + ch * 8;
                CP16(dst + row * 128 + ((ch ^ (row & 7)) << 4), src);
            }
        };
        auto loadB = [&](int st, int kt) {
            uint32_t dst = su + st * STB + 16384;
            int k0 = kt * 64;
#pragma unroll
            for (int p = 0; p < 4; p++) {
                int c = tid + p * 256;
                int row = c >> 3, ch = c & 7;
                const __half* src = Bb + (long long)(n0 + row) * ldb + k0 + ch * 8;
                CP16(dst + row * 128 + ((ch ^ (row & 7)) << 4), src);
            }
        };
        loadA(0, 0); loadB(0, 0); CP_COMMIT();
        if (KT > 1) { loadA(1, 1); loadB(1, 1); CP_COMMIT(); }
        int st = 0, stn = 2;
        for (int i = 0; i < KT; i++) {
            if (i < KT - 1) { CP_WAIT(1); } else { CP_WAIT(0); }
            __syncthreads();
            if (i + 2 < KT) {
                loadA(stn, i + 2); loadB(stn, i + 2); CP_COMMIT();
                stn = (stn == 2) ? 0 : stn + 1;
            }
            uint32_t Abase = su + st * STB;
            uint32_t Bbase = Abase + 16384;
            st = (st == 2) ? 0 : st + 1;
#pragma unroll
            for (int kk = 0; kk < 4; kk++) {
                uint32_t af[4][4], bf[4][2];
                int cA = ((kk * 2 + ti.cxA) ^ ti.lr) << 4;
                int cB = ((kk * 2 + ti.cxB) ^ ti.lr) << 4;
#pragma unroll
                for (int mt = 0; mt < 4; mt++)
                    LDM4(af[mt][0], af[mt][1], af[mt][2], af[mt][3], Abase + ti.rA[mt] + cA);
                LDM4(bf[0][0], bf[0][1], bf[1][0], bf[1][1], Bbase + ti.rB[0] + cB);
                LDM4(bf[2][0], bf[2][1], bf[3][0], bf[3][1], Bbase + ti.rB[1] + cB);
#pragma unroll
                for (int mt = 0; mt < 4; mt++)
#pragma unroll
                    for (int nt = 0; nt < 4; nt++)
                        MMA16(acc[mt][nt], af[mt], bf[nt]);
            }
            __syncthreads();
        }
    };

    // Phase 1: Q @ S
    phase(qkvh + (long long)u * 1048576, 4096,
          Ph + (long long)u * 1048576, 1024, 16);
    // Phase 2: attn @ V  (causal-truncated K)
    int K2 = (m0 + 128 < CHUNK) ? (m0 + 128) : CHUNK;
    phase(attnh + (long long)u * 65536, 256,
          vT + (long long)ub * 4194304 + uc * 256, 4096, K2 >> 6);

    // epilogue: / den -> fp16
    __half* Ch = numh + (long long)u * 262144;
#pragma unroll
    for (int mt = 0; mt < 4; mt++) {
        int row0 = m0 + ti.wm + mt * 16 + ti.l4q;
        int row1 = row0 + 8;
        float rcp0 = __frcp_rn(den[(long long)u * CHUNK + row0]);
        float rcp1 = __frcp_rn(den[(long long)u * CHUNK + row1]);
#pragma unroll
        for (int nt = 0; nt < 4; nt++) {
            int col = n0 + ti.wn + nt * 8 + ti.lmq * 2;
            __half2 h0 = __floats2half2_rn(acc[mt][nt][0] * rcp0, acc[mt][nt][1] * rcp0);
            __half2 h1 = __floats2half2_rn(acc[mt][nt][2] * rcp1, acc[mt][nt][3] * rcp1);
            *reinterpret_cast<__half2*>(Ch + (long long)row0 * 1024 + col) = h0;
            *reinterpret_cast<__half2*>(Ch + (long long)row1 * 1024 + col) = h1;
        }
    }
}

// ---------------- LayerNorm -> fp16 -------------------------------------------
__global__ void ln_kernel(const float* __restrict__ x,
                          const float* __restrict__ g,
                          const float* __restrict__ b,
                          __half* __restrict__ xn) {
    int row = blockIdx.x;
    const float* xr = x + (size_t)row * D_MODEL;
    __half* outr = xn + (size_t)row * D_MODEL;
    int tid = threadIdx.x;
    float vals[4];
    float s = 0.f, ss = 0.f;
#pragma unroll
    for (int i = 0; i < 4; i++) {
        float v = xr[tid + i * 256];
        vals[i] = v; s += v; ss += v * v;
    }
#pragma unroll
    for (int o = 16; o > 0; o >>= 1) {
        s  += __shfl_xor_sync(0xffffffffu, s, o);
        ss += __shfl_xor_sync(0xffffffffu, ss, o);
    }
    __shared__ float sbuf[8], ssbuf[8];
    int warp = tid >> 5, lane = tid & 31;
    if (lane == 0) { sbuf[warp] = s; ssbuf[warp] = ss; }
    __syncthreads();
    float ts = 0.f, tss = 0.f;
#pragma unroll
    for (int wq = 0; wq < 8; wq++) { ts += sbuf[wq]; tss += ssbuf[wq]; }
    float mu = ts * (1.0f / D_MODEL);
    float var = tss * (1.0f / D_MODEL) - mu * mu;
    float inv = rsqrtf(var + LN_EPS);
#pragma unroll
    for (int i = 0; i < 4; i++) {
        int d = tid + i * 256;
        outr[d] = __float2half_rn((vals[i] - mu) * inv * g[d] + b[d]);
    }
}

// ---------------- weight prepack (fp16, transposed) ---------------------------
__global__ void pack_w(const float* __restrict__ wq, const float* __restrict__ wg,
                       __half* __restrict__ wt) {
    long long idx = (long long)blockIdx.x * 256 + threadIdx.x;  // n*1024 + k
    int n = (int)(idx >> 10);
    int k = (int)(idx & 1023);
    float v = (n < 3072) ? wq[(long long)k * 3072 + n] : wg[(long long)k * 1024 + n - 3072];
    wt[idx] = __float2half_rn(v);
}
__global__ void pack_bias(const float* __restrict__ bq, const float* __restrict__ bg,
                          float* __restrict__ bc) {
    int n = blockIdx.x * 256 + threadIdx.x;
    bc[n] = (n < 3072) ? bq[n] : bg[n - 3072];
}
__global__ void pack_wp(const float* __restrict__ wp, __half* __restrict__ wpT) {
    long long idx = (long long)blockIdx.x * 256 + threadIdx.x;
    int n = (int)(idx >> 10);
    int k = (int)(idx & 1023);
    wpT[idx] = __float2half_rn(wp[(long long)k * 1024 + n]);
}

// ---------------- dummy (launch-order pad so ncu -s 5 captures qkvg GEMM) ----
__global__ void zden_kernel(float* __restrict__ den) {
    den[blockIdx.x * 256 + threadIdx.x] = 0.f;
}

// ---------------- fused activations + kv transpose ----------------------------
// q = elu(q)+1 (in place); k = elu(k*sigmoid(gate))+1 (in place + kT transposed);
// v -> vT transposed.
__global__ void actT_kernel(__half* __restrict__ qkvh,
                            __half* __restrict__ kT, __half* __restrict__ vT) {
    __shared__ __half sk[32][33], sv[32][33];
    int tx = threadIdx.x, ty = threadIdx.y;
    int t0 = blockIdx.x * 32, d0 = blockIdx.y * 32;
#pragma unroll
    for (int i = 0; i < 4; i++) {
        long long r = t0 + ty + i * 8;
        __half* base = qkvh + r * 4096;
        int d = d0 + tx;
        float q  = __half2float(base[d]);
        float k  = __half2float(base[1024 + d]);
        float gt = __half2float(base[3072 + d]);
        float sg = 1.f / (1.f + expf(-gt));
        float kg = k * sg;
        q  = (q  > 0.f ? q  : expm1f(q))  + 1.f;
        kg = (kg > 0.f ? kg : expm1f(kg)) + 1.f;
        __half qh = __float2half_rn(q);
        __half kh = __float2half_rn(kg);
        base[d] = qh;
        base[1024 + d] = kh;
        sk[ty + i * 8][tx] = kh;
        sv[ty + i * 8][tx] = base[2048 + d];
    }
    __syncthreads();
    int tg = t0 + tx;
    int b = tg >> 12, t = tg & 4095;
#pragma unroll
    for (int i = 0; i < 4; i++) {
        int d = d0 + ty + i * 8;
        long long o = ((long long)b * 1024 + d) * 4096 + t;
        kT[o] = sk[tx][ty + i * 8];
        vT[o] = sv[tx][ty + i * 8];
    }
}

// ---------------- per-chunk K column sums (contiguous reads from kT) ----------
__global__ void ksum_kernel(const __half* __restrict__ kT, float* __restrict__ pk) {
    int row = blockIdx.x * 8 + (threadIdx.x >> 5);   // b*1024 + d
    int lane = threadIdx.x & 31;
    const __half* base = kT + (long long)row * 4096;
    int b = row >> 10, d = row & 1023;
    for (int c = 0; c < NCHUNK; c++) {
        const __half* p = base + c * 256 + lane * 8;
        float s = 0.f;
#pragma unroll
        for (int j = 0; j < 8; j++) s += __half2float(p[j]);
#pragma unroll
        for (int o = 16; o > 0; o >>= 1) s += __shfl_xor_sync(0xffffffffu, s, o);
        if (lane == 0) pk[(b * NCHUNK + c) * D_MODEL + d] = s;
    }
}

// ---------------- exclusive prefix over chunks --------------------------------
__global__ void prefix_p(__half* __restrict__ P) {
    long long e = (long long)blockIdx.x * 256 + threadIdx.x;
    int b = (int)(e >> 20);
    long long off = e & 1048575;
    __half* base = P + (long long)b * NCHUNK * 1048576 + off;
    float run = 0.f;
#pragma unroll
    for (int c = 0; c < NCHUNK; c++) {
        float t = __half2float(base[(long long)c * 1048576]);
        base[(long long)c * 1048576] = __float2half_rn(run);
        run += t;
    }
}

__global__ void prefix_k(float* __restrict__ Pk) {
    int e = blockIdx.x * 256 + threadIdx.x;
    int b = e >> 10;
    int d = e & 1023;
    float* base = Pk + b * NCHUNK * D_MODEL + d;
    float run = 0.f;
#pragma unroll
    for (int c = 0; c < NCHUNK; c++) {
        float t = base[c * D_MODEL];
        base[c * D_MODEL] = run;
        run += t;
    }
}

// ---------------- den = eps + q . Sk ------------------------------------------
__global__ void den_kernel(const __half* __restrict__ qkvh,
                           const float* __restrict__ pk,
                           float* __restrict__ den) {
    int warp = blockIdx.x * 8 + (threadIdx.x >> 5);
    int lane = threadIdx.x & 31;
    const __half* q = qkvh + (long long)warp * 4096;
    const float* sk = pk + (warp / CHUNK) * D_MODEL;
    float s = 0.f;
#pragma unroll 8
    for (int i = lane; i < D_MODEL; i += 32) s += __half2float(q[i]) * sk[i];
#pragma unroll
    for (int o = 16; o > 0; o >>= 1) s += __shfl_xor_sync(0xffffffffu, s, o);
    if (lane == 0) den[warp] = s + DEN_EPS;
}

// ---------------- launch ------------------------------------------------------
extern "C" void kernel_launch(void* const* d_in, const int* in_sizes, int n_in,
                              void* d_out, int out_size) {
    const float* x      = (const float*)d_in[0];
    const float* w_qkv  = (const float*)d_in[1];
    const float* b_qkv  = (const float*)d_in[2];
    const float* w_gate = (const float*)d_in[3];
    const float* b_gate = (const float*)d_in[4];
    const float* w_proj = (const float*)d_in[5];
    const float* b_proj = (const float*)d_in[6];
    const float* ln_g   = (const float*)d_in[7];
    const float* ln_b   = (const float*)d_in[8];
    float* out = (float*)d_out;

    __half *p_xnh, *p_qkvh, *p_kT, *p_vT, *p_Ph, *p_attnh, *p_numh, *p_wth, *p_wph;
    float *p_Pk, *p_den, *p_bcat;
    cudaGetSymbolAddress((void**)&p_xnh,   g_xnh);
    cudaGetSymbolAddress((void**)&p_qkvh,  g_qkvh);
    cudaGetSymbolAddress((void**)&p_kT,    g_kT);
    cudaGetSymbolAddress((void**)&p_vT,    g_vT);
    cudaGetSymbolAddress((void**)&p_Ph,    g_Ph);
    cudaGetSymbolAddress((void**)&p_Pk,    g_Pk);
    cudaGetSymbolAddress((void**)&p_attnh, g_attnh);
    cudaGetSymbolAddress((void**)&p_numh,  g_numh);
    cudaGetSymbolAddress((void**)&p_den,   g_den);
    cudaGetSymbolAddress((void**)&p_wth,   g_wth);
    cudaGetSymbolAddress((void**)&p_wph,   g_wph);
    cudaGetSymbolAddress((void**)&p_bcat,  g_bcat);

    cudaFuncSetAttribute(hgemm<1>, cudaFuncAttributeMaxDynamicSharedMemorySize, SMEM_BYTES);
    cudaFuncSetAttribute(hgemm<2>, cudaFuncAttributeMaxDynamicSharedMemorySize, SMEM_BYTES);
    cudaFuncSetAttribute(hgemm<3>, cudaFuncAttributeMaxDynamicSharedMemorySize, SMEM_BYTES);
    cudaFuncSetAttribute(hgemm<5>, cudaFuncAttributeMaxDynamicSharedMemorySize, SMEM_BYTES);
    cudaFuncSetAttribute(num_kernel, cudaFuncAttributeMaxDynamicSharedMemorySize, SMEM_BYTES);

#define UNI(s) 16LL * (s), (long long)(s)

    // 0-3. prepack + LN
    pack_w   <<<(4096 * 1024) / 256, 256>>>(w_qkv, w_gate, p_wth);       // launch 0
    pack_bias<<<4096 / 256, 256>>>(b_qkv, b_gate, p_bcat);               // launch 1
    pack_wp  <<<(1024 * 1024) / 256, 256>>>(w_proj, p_wph);              // launch 2
    ln_kernel<<<NROWS, 256>>>(x, ln_g, ln_b, p_xnh);                     // launch 3
    zden_kernel<<<NROWS / 256, 256>>>(p_den);                            // launch 4 (pad)

    // 5. qkvg = xn @ [w_qkv|w_gate] + bias  -> qkvh fp16   (ncu -s 5 target)
    hgemm<5><<<dim3(32, 128, 1), 256, SMEM_BYTES>>>(
        p_xnh, 1024, UNI(0), p_wth, 1024, UNI(0),
        p_qkvh, 4096, 0, p_bcat, nullptr, 1024);

    // 6. fused activations + kv transpose
    actT_kernel<<<dim3(NROWS / 32, D_MODEL / 32), dim3(32, 8)>>>(p_qkvh, p_kT, p_vT);

    // 7. per-chunk K colsums (from kT)
    ksum_kernel<<<(B_SZ * D_MODEL) / 8, 256>>>(p_kT, p_Pk);

    // 8. Pt_u = V_u^T @ K_u -> Ph fp16
    hgemm<2><<<dim3(8, 8, NUNITS), 256, SMEM_BYTES>>>(
        p_vT, 4096, 4194304LL, 256LL, p_kT, 4096, 4194304LL, 256LL,
        p_Ph, 1024, 1048576LL, nullptr, nullptr, 256);

    // 9. exclusive prefix scans
    prefix_p<<<(B_SZ * 1048576) / 256, 256>>>(p_Ph);
    prefix_k<<<(B_SZ * D_MODEL) / 256, 256>>>(p_Pk);

    // 10. den = eps + q . Sk  (before attn atomics)
    den_kernel<<<NROWS / 8, 256>>>(p_qkvh, p_Pk, p_den);

    // 11. attn = tril(Q_u @ K_u^T) -> fp16, rowsums -> den
    hgemm<3><<<dim3(2, 2, NUNITS), 256, SMEM_BYTES>>>(
        p_qkvh, 4096, UNI(1048576LL), p_qkvh + 1024, 4096, UNI(1048576LL),
        p_attnh, 256, 65536LL, nullptr, p_den, 1024);

    // 12. num = (Q@S + attn@V) / den -> fp16  (fused, no fp32 intermediate)
    num_kernel<<<dim3(8, 2, NUNITS), 256, SMEM_BYTES>>>(
        p_qkvh, p_Ph, p_attnh, p_vT, p_den, p_numh);

    // 13. out = numh @ w_proj + b_proj
    hgemm<1><<<dim3(8, 128, 1), 256, SMEM_BYTES>>>(
        p_numh, 1024, UNI(0), p_wph, 1024, UNI(0),
        out, 1024, 0, b_proj, nullptr, 1024);
}

// round 7
// speedup vs baseline: 8.3407x; 1.1994x over previous
#include <cuda_runtime.h>
#include <cuda_fp16.h>
#include <cstdint>
#include <math.h>

#define D_MODEL 1024
#define B_SZ 4
#define T_SZ 4096
#define NROWS (B_SZ * T_SZ)          /* 16384 */
#define CHUNK 512
#define NCHUNK (T_SZ / CHUNK)        /* 8 */
#define NUNITS (B_SZ * NCHUNK)       /* 32 */
#define LN_EPS 1e-5f
#define DEN_EPS 1e-6f

// ---------------- scratch (device globals; no allocations allowed) -----------
__device__ __half g_xnh[(size_t)NROWS * D_MODEL];                  // 32 MB
__device__ __half g_qkvh[(size_t)NROWS * 4 * D_MODEL];             // 128 MB q|k|v|gate
__device__ __half g_kT[(size_t)B_SZ * D_MODEL * T_SZ];             // 32 MB [b][d][t]
__device__ __half g_vT[(size_t)B_SZ * D_MODEL * T_SZ];             // 32 MB
__device__ __half g_Ph[(size_t)NUNITS * D_MODEL * D_MODEL];        // 64 MB Pt planes -> excl prefix
__device__ float  g_Pk[NUNITS * D_MODEL];
__device__ __half g_attnh[(size_t)NUNITS * CHUNK * CHUNK];         // 16 MB
__device__ __half g_numh[(size_t)NROWS * D_MODEL];                 // 32 MB
__device__ float  g_den[NROWS];
__device__ __half g_wth[(size_t)4096 * 1024];                      // qkv|gate weights [n][k]
__device__ __half g_wph[(size_t)1024 * 1024];                      // w_proj^T [n][k]
__device__ float  g_bcat[4096];

// tril block map for 512x512 attn tile (10 blocks of 128x128)
__constant__ int c_bm[10] = {0, 1, 1, 2, 2, 2, 3, 3, 3, 3};
__constant__ int c_bn[10] = {0, 0, 1, 0, 1, 2, 0, 1, 2, 3};

// ---------------- helpers -----------------------------------------------------
__device__ __forceinline__ uint32_t smem_u32(const void* p) {
    uint32_t a;
    asm("{ .reg .u64 t; cvta.to.shared.u64 t, %1; cvt.u32.u64 %0, t; }" : "=r"(a) : "l"(p));
    return a;
}

#define CP16(dst, src) \
    asm volatile("cp.async.cg.shared.global [%0], [%1], 16;" :: "r"(dst), "l"(src))
#define CP_COMMIT() asm volatile("cp.async.commit_group;" ::: "memory")
#define CP_WAIT(n)  asm volatile("cp.async.wait_group %0;" :: "n"(n) : "memory")

#define LDM4(r0, r1, r2, r3, addr) \
    asm volatile("ldmatrix.sync.aligned.m8n8.x4.shared.b16 {%0,%1,%2,%3}, [%4];" \
                 : "=r"(r0), "=r"(r1), "=r"(r2), "=r"(r3) : "r"(addr))

#define MMA16(c, a, b) \
    asm volatile( \
        "mma.sync.aligned.m16n8k16.row.col.f32.f16.f16.f32 " \
        "{%0,%1,%2,%3}, {%4,%5,%6,%7}, {%8,%9}, {%0,%1,%2,%3};" \
        : "+f"((c)[0]), "+f"((c)[1]), "+f"((c)[2]), "+f"((c)[3]) \
        : "r"((a)[0]), "r"((a)[1]), "r"((a)[2]), "r"((a)[3]), \
          "r"((b)[0]), "r"((b)[1]))

#define STB 32768                   /* stage bytes: A 16KB + B 16KB */
#define SMEM_BYTES (3 * STB)        /* 98304 */

// Common warp/fragment indexing for the 128x128 tile, 8 warps (2M x 4N)
struct TileIdx {
    int lane, w, wm, wn, g, lr, l4q, lmq, cxA, cxB;
    int rA[4], rB[2];
    __device__ __forceinline__ TileIdx(int tid) {
        lane = tid & 31; w = tid >> 5;
        wm = (w & 1) * 64; wn = (w >> 1) * 32;
        g = lane >> 3; lr = lane & 7;
        l4q = lane >> 2; lmq = lane & 3;
        cxA = (g >> 1); cxB = (g & 1);
#pragma unroll
        for (int mt = 0; mt < 4; mt++) rA[mt] = (wm + mt * 16 + lr + 8 * (g & 1)) * 128;
#pragma unroll
        for (int p = 0; p < 2; p++) rB[p] = (wn + p * 16 + lr + 8 * (g >> 1)) * 128;
    }
};

// ---------------- fp16 tensor-core GEMM ---------------------------------------
// EPI: 1 bias+f32 out, 2 half out (P GEMM; skip last chunk), 3 tril-mapped
//      attn: mask+half out+rowsum->den, 5 bias+half out.
template <int EPI>
__global__ void __launch_bounds__(256, 2) hgemm(
    const __half* __restrict__ A, int lda, long long sAb, long long sAc,
    const __half* __restrict__ B, int ldb, long long sBb, long long sBc,
    void* __restrict__ C, int ldc, long long sC,
    const float* __restrict__ bias, float* __restrict__ den, int K) {
    extern __shared__ char sm[];
    const uint32_t su = smem_u32(sm);
    const int tid = threadIdx.x;
    const int u = blockIdx.z;
    const int ub = u >> 3, uc = u & 7;

    if (EPI == 2 && uc == NCHUNK - 1) return;   // last chunk's P never consumed

    const __half* Ab = A + ub * sAb + uc * sAc;
    const __half* Bb = B + ub * sBb + uc * sBc;
    int m0, n0;
    if (EPI == 3) { m0 = c_bm[blockIdx.x] * 128; n0 = c_bn[blockIdx.x] * 128; }
    else          { m0 = blockIdx.y * 128;       n0 = blockIdx.x * 128; }

    const TileIdx ti(tid);

    auto loadA = [&](int st, int kt) {
        uint32_t dst = su + st * STB;
        int k0 = kt * 64;
#pragma unroll
        for (int p = 0; p < 4; p++) {
            int c = tid + p * 256;
            int row = c >> 3, ch = c & 7;
            const __half* src = Ab + (long long)(m0 + row) * lda + k0 + ch * 8;
            CP16(dst + row * 128 + ((ch ^ (row & 7)) << 4), src);
        }
    };
    auto loadB = [&](int st, int kt) {
        uint32_t dst = su + st * STB + 16384;
        int k0 = kt * 64;
#pragma unroll
        for (int p = 0; p < 4; p++) {
            int c = tid + p * 256;
            int row = c >> 3, ch = c & 7;
            const __half* src = Bb + (long long)(n0 + row) * ldb + k0 + ch * 8;
            CP16(dst + row * 128 + ((ch ^ (row & 7)) << 4), src);
        }
    };

    float acc[4][4][4];
#pragma unroll
    for (int mt = 0; mt < 4; mt++)
#pragma unroll
        for (int nt = 0; nt < 4; nt++)
#pragma unroll
            for (int r = 0; r < 4; r++) acc[mt][nt][r] = 0.f;

    const int KT = K >> 6;
    loadA(0, 0); loadB(0, 0); CP_COMMIT();
    if (KT > 1) { loadA(1, 1); loadB(1, 1); CP_COMMIT(); }

    int st = 0, stn = 2;
    for (int i = 0; i < KT; i++) {
        if (i < KT - 1) { CP_WAIT(1); } else { CP_WAIT(0); }
        __syncthreads();
        if (i + 2 < KT) {
            loadA(stn, i + 2); loadB(stn, i + 2); CP_COMMIT();
            stn = (stn == 2) ? 0 : stn + 1;
        }
        uint32_t Abase = su + st * STB;
        uint32_t Bbase = Abase + 16384;
        st = (st == 2) ? 0 : st + 1;
#pragma unroll
        for (int kk = 0; kk < 4; kk++) {
            uint32_t af[4][4], bf[4][2];
            int cA = ((kk * 2 + ti.cxA) ^ ti.lr) << 4;
            int cB = ((kk * 2 + ti.cxB) ^ ti.lr) << 4;
#pragma unroll
            for (int mt = 0; mt < 4; mt++)
                LDM4(af[mt][0], af[mt][1], af[mt][2], af[mt][3], Abase + ti.rA[mt] + cA);
            LDM4(bf[0][0], bf[0][1], bf[1][0], bf[1][1], Bbase + ti.rB[0] + cB);
            LDM4(bf[2][0], bf[2][1], bf[3][0], bf[3][1], Bbase + ti.rB[1] + cB);
#pragma unroll
            for (int mt = 0; mt < 4; mt++)
#pragma unroll
                for (int nt = 0; nt < 4; nt++)
                    MMA16(acc[mt][nt], af[mt], bf[nt]);
        }
        __syncthreads();
    }

    // ---- epilogue ----
    float* Cf = (float*)C + (long long)u * sC;
    __half* Ch = (__half*)C + (long long)u * sC;

#pragma unroll
    for (int mt = 0; mt < 4; mt++) {
        int row0 = m0 + ti.wm + mt * 16 + ti.l4q;
        int row1 = row0 + 8;
        float rs0 = 0.f, rs1 = 0.f;
#pragma unroll
        for (int nt = 0; nt < 4; nt++) {
            int col = n0 + ti.wn + nt * 8 + ti.lmq * 2;
            float v0 = acc[mt][nt][0], v1 = acc[mt][nt][1];
            float v2 = acc[mt][nt][2], v3 = acc[mt][nt][3];
            if (EPI == 1 || EPI == 5) {
                float b0 = bias[col], b1 = bias[col + 1];
                v0 += b0; v1 += b1; v2 += b0; v3 += b1;
            }
            if (EPI == 3) {
                v0 = (col     > row0) ? 0.f : v0;
                v1 = (col + 1 > row0) ? 0.f : v1;
                v2 = (col     > row1) ? 0.f : v2;
                v3 = (col + 1 > row1) ? 0.f : v3;
            }
            if (EPI == 1) {
                *reinterpret_cast<float2*>(Cf + (long long)row0 * ldc + col) = make_float2(v0, v1);
                *reinterpret_cast<float2*>(Cf + (long long)row1 * ldc + col) = make_float2(v2, v3);
            } else {
                __half2 h0 = __floats2half2_rn(v0, v1);
                __half2 h1 = __floats2half2_rn(v2, v3);
                if (EPI == 3) {
                    rs0 += __half2float(h0.x) + __half2float(h0.y);
                    rs1 += __half2float(h1.x) + __half2float(h1.y);
                }
                *reinterpret_cast<__half2*>(Ch + (long long)row0 * ldc + col) = h0;
                *reinterpret_cast<__half2*>(Ch + (long long)row1 * ldc + col) = h1;
            }
        }
        if (EPI == 3) {
            rs0 += __shfl_xor_sync(0xffffffffu, rs0, 1);
            rs0 += __shfl_xor_sync(0xffffffffu, rs0, 2);
            rs1 += __shfl_xor_sync(0xffffffffu, rs1, 1);
            rs1 += __shfl_xor_sync(0xffffffffu, rs1, 2);
            if (ti.lmq == 0) {
                atomicAdd(den + (long long)u * CHUNK + row0, rs0);
                atomicAdd(den + (long long)u * CHUNK + row1, rs1);
            }
        }
    }
}

// ---------------- fused num kernel: num = (Q@S + attn@V) / den -> fp16 --------
__global__ void __launch_bounds__(256, 2) num_kernel(
    const __half* __restrict__ qkvh, const __half* __restrict__ Ph,
    const __half* __restrict__ attnh, const __half* __restrict__ vT,
    const float* __restrict__ den, __half* __restrict__ numh) {
    extern __shared__ char sm[];
    const uint32_t su = smem_u32(sm);
    const int tid = threadIdx.x;
    const int u = blockIdx.z;
    const int ub = u >> 3, uc = u & 7;
    const int m0 = blockIdx.y * 128;
    const int n0 = blockIdx.x * 128;
    const TileIdx ti(tid);

    float acc[4][4][4];
#pragma unroll
    for (int mt = 0; mt < 4; mt++)
#pragma unroll
        for (int nt = 0; nt < 4; nt++)
#pragma unroll
            for (int r = 0; r < 4; r++) acc[mt][nt][r] = 0.f;

    auto phase = [&](const __half* Ab, int lda, const __half* Bb, int ldb, int KT) {
        auto loadA = [&](int st, int kt) {
            uint32_t dst = su + st * STB;
            int k0 = kt * 64;
#pragma unroll
            for (int p = 0; p < 4; p++) {
                int c = tid + p * 256;
                int row = c >> 3, ch = c & 7;
                const __half* src = Ab + (long long)(m0 + row) * lda + k0 + ch * 8;
                CP16(dst + row * 128 + ((ch ^ (row & 7)) << 4), src);
            }
        };
        auto loadB = [&](int st, int kt) {
            uint32_t dst = su + st * STB + 16384;
            int k0 = kt * 64;
#pragma unroll
            for (int p = 0; p < 4; p++) {
                int c = tid + p * 256;
                int row = c >> 3, ch = c & 7;
                const __half* src = Bb + (long long)(n0 + row) * ldb + k0 + ch * 8;
                CP16(dst + row * 128 + ((ch ^ (row & 7)) << 4), src);
            }
        };
        loadA(0, 0); loadB(0, 0); CP_COMMIT();
        if (KT > 1) { loadA(1, 1); loadB(1, 1); CP_COMMIT(); }
        int st = 0, stn = 2;
        for (int i = 0; i < KT; i++) {
            if (i < KT - 1) { CP_WAIT(1); } else { CP_WAIT(0); }
            __syncthreads();
            if (i + 2 < KT) {
                loadA(stn, i + 2); loadB(stn, i + 2); CP_COMMIT();
                stn = (stn == 2) ? 0 : stn + 1;
            }
            uint32_t Abase = su + st * STB;
            uint32_t Bbase = Abase + 16384;
            st = (st == 2) ? 0 : st + 1;
#pragma unroll
            for (int kk = 0; kk < 4; kk++) {
                uint32_t af[4][4], bf[4][2];
                int cA = ((kk * 2 + ti.cxA) ^ ti.lr) << 4;
                int cB = ((kk * 2 + ti.cxB) ^ ti.lr) << 4;
#pragma unroll
                for (int mt = 0; mt < 4; mt++)
                    LDM4(af[mt][0], af[mt][1], af[mt][2], af[mt][3], Abase + ti.rA[mt] + cA);
                LDM4(bf[0][0], bf[0][1], bf[1][0], bf[1][1], Bbase + ti.rB[0] + cB);
                LDM4(bf[2][0], bf[2][1], bf[3][0], bf[3][1], Bbase + ti.rB[1] + cB);
#pragma unroll
                for (int mt = 0; mt < 4; mt++)
#pragma unroll
                    for (int nt = 0; nt < 4; nt++)
                        MMA16(acc[mt][nt], af[mt], bf[nt]);
            }
            __syncthreads();
        }
    };

    // Phase 1: Q @ S   (S_0 = 0 -> skip for first chunk of each batch)
    if (uc != 0)
        phase(qkvh + (long long)u * CHUNK * 4096, 4096,
              Ph + (long long)u * 1048576, 1024, 16);
    // Phase 2: attn @ V  (causal-truncated K)
    int K2 = m0 + 128;
    phase(attnh + (long long)u * CHUNK * CHUNK, CHUNK,
          vT + (long long)ub * 4194304 + uc * CHUNK, 4096, K2 >> 6);

    // epilogue: / den -> fp16
    __half* Ch = numh + (long long)u * CHUNK * 1024;
#pragma unroll
    for (int mt = 0; mt < 4; mt++) {
        int row0 = m0 + ti.wm + mt * 16 + ti.l4q;
        int row1 = row0 + 8;
        float rcp0 = __frcp_rn(den[(long long)u * CHUNK + row0]);
        float rcp1 = __frcp_rn(den[(long long)u * CHUNK + row1]);
#pragma unroll
        for (int nt = 0; nt < 4; nt++) {
            int col = n0 + ti.wn + nt * 8 + ti.lmq * 2;
            __half2 h0 = __floats2half2_rn(acc[mt][nt][0] * rcp0, acc[mt][nt][1] * rcp0);
            __half2 h1 = __floats2half2_rn(acc[mt][nt][2] * rcp1, acc[mt][nt][3] * rcp1);
            *reinterpret_cast<__half2*>(Ch + (long long)row0 * 1024 + col) = h0;
            *reinterpret_cast<__half2*>(Ch + (long long)row1 * 1024 + col) = h1;
        }
    }
}

// ---------------- LayerNorm -> fp16 -------------------------------------------
__global__ void ln_kernel(const float* __restrict__ x,
                          const float* __restrict__ g,
                          const float* __restrict__ b,
                          __half* __restrict__ xn) {
    int row = blockIdx.x;
    const float* xr = x + (size_t)row * D_MODEL;
    __half* outr = xn + (size_t)row * D_MODEL;
    int tid = threadIdx.x;
    float vals[4];
    float s = 0.f, ss = 0.f;
#pragma unroll
    for (int i = 0; i < 4; i++) {
        float v = xr[tid + i * 256];
        vals[i] = v; s += v; ss += v * v;
    }
#pragma unroll
    for (int o = 16; o > 0; o >>= 1) {
        s  += __shfl_xor_sync(0xffffffffu, s, o);
        ss += __shfl_xor_sync(0xffffffffu, ss, o);
    }
    __shared__ float sbuf[8], ssbuf[8];
    int warp = tid >> 5, lane = tid & 31;
    if (lane == 0) { sbuf[warp] = s; ssbuf[warp] = ss; }
    __syncthreads();
    float ts = 0.f, tss = 0.f;
#pragma unroll
    for (int wq = 0; wq < 8; wq++) { ts += sbuf[wq]; tss += ssbuf[wq]; }
    float mu = ts * (1.0f / D_MODEL);
    float var = tss * (1.0f / D_MODEL) - mu * mu;
    float inv = rsqrtf(var + LN_EPS);
#pragma unroll
    for (int i = 0; i < 4; i++) {
        int d = tid + i * 256;
        outr[d] = __float2half_rn((vals[i] - mu) * inv * g[d] + b[d]);
    }
}

// ---------------- weight prepack (fp16, transposed) ---------------------------
__global__ void pack_w(const float* __restrict__ wq, const float* __restrict__ wg,
                       __half* __restrict__ wt) {
    long long idx = (long long)blockIdx.x * 256 + threadIdx.x;  // n*1024 + k
    int n = (int)(idx >> 10);
    int k = (int)(idx & 1023);
    float v = (n < 3072) ? wq[(long long)k * 3072 + n] : wg[(long long)k * 1024 + n - 3072];
    wt[idx] = __float2half_rn(v);
}
__global__ void pack_bias(const float* __restrict__ bq, const float* __restrict__ bg,
                          float* __restrict__ bc) {
    int n = blockIdx.x * 256 + threadIdx.x;
    bc[n] = (n < 3072) ? bq[n] : bg[n - 3072];
}
__global__ void pack_wp(const float* __restrict__ wp, __half* __restrict__ wpT) {
    long long idx = (long long)blockIdx.x * 256 + threadIdx.x;
    int n = (int)(idx >> 10);
    int k = (int)(idx & 1023);
    wpT[idx] = __float2half_rn(wp[(long long)k * 1024 + n]);
}

// ---------------- zero Pk (accumulated by actT atomics) -----------------------
__global__ void zpk_kernel(float* __restrict__ pk) {
    pk[blockIdx.x * 256 + threadIdx.x] = 0.f;
}

// ---------------- fused activations + kv transpose + chunk K colsums ----------
__global__ void actT_kernel(__half* __restrict__ qkvh,
                            __half* __restrict__ kT, __half* __restrict__ vT,
                            float* __restrict__ pk) {
    __shared__ __half sk[32][33], sv[32][33];
    __shared__ float ss[8][32];
    int tx = threadIdx.x, ty = threadIdx.y;
    int t0 = blockIdx.x * 32, d0 = blockIdx.y * 32;
    float ksum = 0.f;
#pragma unroll
    for (int i = 0; i < 4; i++) {
        long long r = t0 + ty + i * 8;
        __half* base = qkvh + r * 4096;
        int d = d0 + tx;
        float q  = __half2float(base[d]);
        float k  = __half2float(base[1024 + d]);
        float gt = __half2float(base[3072 + d]);
        float sg = 1.f / (1.f + expf(-gt));
        float kg = k * sg;
        q  = (q  > 0.f ? q  : expm1f(q))  + 1.f;
        kg = (kg > 0.f ? kg : expm1f(kg)) + 1.f;
        __half qh = __float2half_rn(q);
        __half kh = __float2half_rn(kg);
        base[d] = qh;
        base[1024 + d] = kh;
        sk[ty + i * 8][tx] = kh;
        sv[ty + i * 8][tx] = base[2048 + d];
        ksum += __half2float(kh);
    }
    ss[ty][tx] = ksum;
    __syncthreads();
    int tg = t0 + tx;
    int b = tg >> 12, t = tg & 4095;
#pragma unroll
    for (int i = 0; i < 4; i++) {
        int d = d0 + ty + i * 8;
        long long o = ((long long)b * 1024 + d) * 4096 + t;
        kT[o] = sk[tx][ty + i * 8];
        vT[o] = sv[tx][ty + i * 8];
    }
    if (ty == 0) {
        float s = 0.f;
#pragma unroll
        for (int j = 0; j < 8; j++) s += ss[j][tx];
        int u = t0 >> 9;   // 512-row chunk unit
        atomicAdd(&pk[u * D_MODEL + d0 + tx], s);
    }
}

// ---------------- exclusive prefix over chunk planes (in place) ---------------
// reads planes 0..6, writes S into planes 1..7 (plane 0 = S_0 = 0, never read).
__global__ void prefix_p(__half* __restrict__ P) {
    long long e = (long long)blockIdx.x * 256 + threadIdx.x;
    int b = (int)(e >> 20);
    long long off = e & 1048575;
    __half* base = P + (long long)b * NCHUNK * 1048576 + off;
    float run = 0.f;
    float nxt = __half2float(base[0]);
#pragma unroll
    for (int c = 1; c < NCHUNK; c++) {
        run += nxt;
        if (c < NCHUNK - 1) nxt = __half2float(base[(long long)c * 1048576]);
        base[(long long)c * 1048576] = __float2half_rn(run);
    }
}

__global__ void prefix_k(float* __restrict__ Pk) {
    int e = blockIdx.x * 256 + threadIdx.x;
    int b = e >> 10;
    int d = e & 1023;
    float* base = Pk + b * NCHUNK * D_MODEL + d;
    float run = 0.f;
#pragma unroll
    for (int c = 0; c < NCHUNK; c++) {
        float t = base[c * D_MODEL];
        base[c * D_MODEL] = run;
        run += t;
    }
}

// ---------------- den = eps + q . Sk ------------------------------------------
__global__ void den_kernel(const __half* __restrict__ qkvh,
                           const float* __restrict__ pk,
                           float* __restrict__ den) {
    int warp = blockIdx.x * 8 + (threadIdx.x >> 5);
    int lane = threadIdx.x & 31;
    const __half* q = qkvh + (long long)warp * 4096;
    const float* sk = pk + (warp / CHUNK) * D_MODEL;
    float s = 0.f;
#pragma unroll 8
    for (int i = lane; i < D_MODEL; i += 32) s += __half2float(q[i]) * sk[i];
#pragma unroll
    for (int o = 16; o > 0; o >>= 1) s += __shfl_xor_sync(0xffffffffu, s, o);
    if (lane == 0) den[warp] = s + DEN_EPS;
}

// ---------------- launch ------------------------------------------------------
extern "C" void kernel_launch(void* const* d_in, const int* in_sizes, int n_in,
                              void* d_out, int out_size) {
    const float* x      = (const float*)d_in[0];
    const float* w_qkv  = (const float*)d_in[1];
    const float* b_qkv  = (const float*)d_in[2];
    const float* w_gate = (const float*)d_in[3];
    const float* b_gate = (const float*)d_in[4];
    const float* w_proj = (const float*)d_in[5];
    const float* b_proj = (const float*)d_in[6];
    const float* ln_g   = (const float*)d_in[7];
    const float* ln_b   = (const float*)d_in[8];
    float* out = (float*)d_out;

    __half *p_xnh, *p_qkvh, *p_kT, *p_vT, *p_Ph, *p_attnh, *p_numh, *p_wth, *p_wph;
    float *p_Pk, *p_den, *p_bcat;
    cudaGetSymbolAddress((void**)&p_xnh,   g_xnh);
    cudaGetSymbolAddress((void**)&p_qkvh,  g_qkvh);
    cudaGetSymbolAddress((void**)&p_kT,    g_kT);
    cudaGetSymbolAddress((void**)&p_vT,    g_vT);
    cudaGetSymbolAddress((void**)&p_Ph,    g_Ph);
    cudaGetSymbolAddress((void**)&p_Pk,    g_Pk);
    cudaGetSymbolAddress((void**)&p_attnh, g_attnh);
    cudaGetSymbolAddress((void**)&p_numh,  g_numh);
    cudaGetSymbolAddress((void**)&p_den,   g_den);
    cudaGetSymbolAddress((void**)&p_wth,   g_wth);
    cudaGetSymbolAddress((void**)&p_wph,   g_wph);
    cudaGetSymbolAddress((void**)&p_bcat,  g_bcat);

    cudaFuncSetAttribute(hgemm<1>, cudaFuncAttributeMaxDynamicSharedMemorySize, SMEM_BYTES);
    cudaFuncSetAttribute(hgemm<2>, cudaFuncAttributeMaxDynamicSharedMemorySize, SMEM_BYTES);
    cudaFuncSetAttribute(hgemm<3>, cudaFuncAttributeMaxDynamicSharedMemorySize, SMEM_BYTES);
    cudaFuncSetAttribute(hgemm<5>, cudaFuncAttributeMaxDynamicSharedMemorySize, SMEM_BYTES);
    cudaFuncSetAttribute(num_kernel, cudaFuncAttributeMaxDynamicSharedMemorySize, SMEM_BYTES);

    // 0-4. prepack + init + LN
    pack_w   <<<(4096 * 1024) / 256, 256>>>(w_qkv, w_gate, p_wth);       // 0
    pack_bias<<<4096 / 256, 256>>>(b_qkv, b_gate, p_bcat);               // 1
    pack_wp  <<<(1024 * 1024) / 256, 256>>>(w_proj, p_wph);              // 2
    zpk_kernel<<<(NUNITS * D_MODEL) / 256, 256>>>(p_Pk);                 // 3
    ln_kernel<<<NROWS, 256>>>(x, ln_g, ln_b, p_xnh);                     // 4

    // 5. qkvg = xn @ [w_qkv|w_gate] + bias  -> qkvh fp16
    hgemm<5><<<dim3(32, 128, 1), 256, SMEM_BYTES>>>(
        p_xnh, 1024, 0, 0, p_wth, 1024, 0, 0,
        p_qkvh, 4096, 0, p_bcat, nullptr, 1024);

    // 6. fused activations + kv transpose + chunk colsums
    actT_kernel<<<dim3(NROWS / 32, D_MODEL / 32), dim3(32, 8)>>>(p_qkvh, p_kT, p_vT, p_Pk);

    // 7. Pt_u = V_u^T @ K_u -> Ph planes (skip last chunk per batch)
    hgemm<2><<<dim3(8, 8, NUNITS), 256, SMEM_BYTES>>>(
        p_vT, 4096, 4194304LL, (long long)CHUNK,
        p_kT, 4096, 4194304LL, (long long)CHUNK,
        p_Ph, 1024, 1048576LL, nullptr, nullptr, CHUNK);

    // 8. exclusive prefix scans
    prefix_p<<<(B_SZ * 1048576) / 256, 256>>>(p_Ph);
    prefix_k<<<(B_SZ * D_MODEL) / 256, 256>>>(p_Pk);

    // 10. den = eps + q . Sk  (before attn atomics)
    den_kernel<<<NROWS / 8, 256>>>(p_qkvh, p_Pk, p_den);

    // 11. attn = tril(Q_u @ K_u^T) -> fp16 (10 tril blocks), rowsums -> den
    hgemm<3><<<dim3(10, 1, NUNITS), 256, SMEM_BYTES>>>(
        p_qkvh, 4096, (long long)NCHUNK * CHUNK * 4096, (long long)CHUNK * 4096,
        p_qkvh + 1024, 4096, (long long)NCHUNK * CHUNK * 4096, (long long)CHUNK * 4096,
        p_attnh, CHUNK, (long long)CHUNK * CHUNK, nullptr, p_den, 1024);

    // 12. num = (Q@S + attn@V) / den -> fp16
    num_kernel<<<dim3(8, 4, NUNITS), 256, SMEM_BYTES>>>(
        p_qkvh, p_Ph, p_attnh, p_vT, p_den, p_numh);

    // 13. out = numh @ w_proj + b_proj
    hgemm<1><<<dim3(8, 128, 1), 256, SMEM_BYTES>>>(
        p_numh, 1024, 0, 0, p_wph, 1024, 0, 0,
        out, 1024, 0, b_proj, nullptr, 1024);
}

// round 8
// speedup vs baseline: 8.4092x; 1.0082x over previous
#include <cuda_runtime.h>
#include <cuda_fp16.h>
#include <cstdint>
#include <math.h>

#define D_MODEL 1024
#define B_SZ 4
#define T_SZ 4096
#define NROWS (B_SZ * T_SZ)          /* 16384 */
#define CHUNK 512
#define NCHUNK (T_SZ / CHUNK)        /* 8 */
#define NUNITS (B_SZ * NCHUNK)       /* 32 */
#define LN_EPS 1e-5f
#define DEN_EPS 1e-6f

// ---------------- scratch (device globals; no allocations allowed) -----------
__device__ __half g_xnh[(size_t)NROWS * D_MODEL];                  // 32 MB
__device__ __half g_qkvh[(size_t)NROWS * 4 * D_MODEL];             // 128 MB q|k|v|gate
__device__ __half g_kT[(size_t)B_SZ * D_MODEL * T_SZ];             // 32 MB [b][d][t]
__device__ __half g_vT[(size_t)B_SZ * D_MODEL * T_SZ];             // 32 MB
__device__ __half g_Ph[(size_t)NUNITS * D_MODEL * D_MODEL];        // 64 MB Pt planes -> excl prefix
__device__ float  g_Pk[NUNITS * D_MODEL];
__device__ __half g_attnh[(size_t)NUNITS * CHUNK * CHUNK];         // 16 MB
__device__ __half g_numh[(size_t)NROWS * D_MODEL];                 // 32 MB
__device__ float  g_den[NROWS];
__device__ __half g_wth[(size_t)4096 * 1024];                      // qkv|gate weights [n][k]
__device__ __half g_wph[(size_t)1024 * 1024];                      // w_proj^T [n][k]
__device__ float  g_bcat[4096];

// tril block map for 512x512 attn tile (10 blocks of 128x128)
__constant__ int c_bm[10] = {0, 1, 1, 2, 2, 2, 3, 3, 3, 3};
__constant__ int c_bn[10] = {0, 0, 1, 0, 1, 2, 0, 1, 2, 3};

// ---------------- helpers -----------------------------------------------------
__device__ __forceinline__ uint32_t smem_u32(const void* p) {
    uint32_t a;
    asm("{ .reg .u64 t; cvta.to.shared.u64 t, %1; cvt.u32.u64 %0, t; }" : "=r"(a) : "l"(p));
    return a;
}

#define CP16(dst, src) \
    asm volatile("cp.async.cg.shared.global [%0], [%1], 16;" :: "r"(dst), "l"(src))
#define CP_COMMIT() asm volatile("cp.async.commit_group;" ::: "memory")
#define CP_WAIT(n)  asm volatile("cp.async.wait_group %0;" :: "n"(n) : "memory")

#define LDM4(r0, r1, r2, r3, addr) \
    asm volatile("ldmatrix.sync.aligned.m8n8.x4.shared.b16 {%0,%1,%2,%3}, [%4];" \
                 : "=r"(r0), "=r"(r1), "=r"(r2), "=r"(r3) : "r"(addr))

#define MMA16(c, a, b) \
    asm volatile( \
        "mma.sync.aligned.m16n8k16.row.col.f32.f16.f16.f32 " \
        "{%0,%1,%2,%3}, {%4,%5,%6,%7}, {%8,%9}, {%0,%1,%2,%3};" \
        : "+f"((c)[0]), "+f"((c)[1]), "+f"((c)[2]), "+f"((c)[3]) \
        : "r"((a)[0]), "r"((a)[1]), "r"((a)[2]), "r"((a)[3]), \
          "r"((b)[0]), "r"((b)[1]))

#define STB 32768                   /* stage bytes: A 16KB + B 16KB */
#define SMEM_BYTES (3 * STB)        /* 98304 */

// Common warp/fragment indexing for the 128x128 tile, 8 warps (2M x 4N)
struct TileIdx {
    int lane, w, wm, wn, g, lr, l4q, lmq, cxA, cxB;
    int rA[4], rB[2];
    __device__ __forceinline__ TileIdx(int tid) {
        lane = tid & 31; w = tid >> 5;
        wm = (w & 1) * 64; wn = (w >> 1) * 32;
        g = lane >> 3; lr = lane & 7;
        l4q = lane >> 2; lmq = lane & 3;
        cxA = (g >> 1); cxB = (g & 1);
#pragma unroll
        for (int mt = 0; mt < 4; mt++) rA[mt] = (wm + mt * 16 + lr + 8 * (g & 1)) * 128;
#pragma unroll
        for (int p = 0; p < 2; p++) rB[p] = (wn + p * 16 + lr + 8 * (g >> 1)) * 128;
    }
};

// ---------------- fp16 tensor-core GEMM ---------------------------------------
// EPI: 1 bias+f32 out, 2 half out (P GEMM; skip last chunk), 3 tril-mapped
//      attn: mask+half out+rowsum->den, 5 bias+half out.
template <int EPI>
__global__ void __launch_bounds__(256, 2) hgemm(
    const __half* __restrict__ A, int lda, long long sAb, long long sAc,
    const __half* __restrict__ B, int ldb, long long sBb, long long sBc,
    void* __restrict__ C, int ldc, long long sC,
    const float* __restrict__ bias, float* __restrict__ den, int K) {
    extern __shared__ char sm[];
    const uint32_t su = smem_u32(sm);
    const int tid = threadIdx.x;
    const int u = blockIdx.z;
    const int ub = u >> 3, uc = u & 7;

    if (EPI == 2 && uc == NCHUNK - 1) return;   // last chunk's P never consumed

    const __half* Ab = A + ub * sAb + uc * sAc;
    const __half* Bb = B + ub * sBb + uc * sBc;
    int m0, n0;
    if (EPI == 3) { m0 = c_bm[blockIdx.x] * 128; n0 = c_bn[blockIdx.x] * 128; }
    else          { m0 = blockIdx.y * 128;       n0 = blockIdx.x * 128; }

    const TileIdx ti(tid);

    auto loadA = [&](int st, int kt) {
        uint32_t dst = su + st * STB;
        int k0 = kt * 64;
#pragma unroll
        for (int p = 0; p < 4; p++) {
            int c = tid + p * 256;
            int row = c >> 3, ch = c & 7;
            const __half* src = Ab + (long long)(m0 + row) * lda + k0 + ch * 8;
            CP16(dst + row * 128 + ((ch ^ (row & 7)) << 4), src);
        }
    };
    auto loadB = [&](int st, int kt) {
        uint32_t dst = su + st * STB + 16384;
        int k0 = kt * 64;
#pragma unroll
        for (int p = 0; p < 4; p++) {
            int c = tid + p * 256;
            int row = c >> 3, ch = c & 7;
            const __half* src = Bb + (long long)(n0 + row) * ldb + k0 + ch * 8;
            CP16(dst + row * 128 + ((ch ^ (row & 7)) << 4), src);
        }
    };

    float acc[4][4][4];
#pragma unroll
    for (int mt = 0; mt < 4; mt++)
#pragma unroll
        for (int nt = 0; nt < 4; nt++)
#pragma unroll
            for (int r = 0; r < 4; r++) acc[mt][nt][r] = 0.f;

    const int KT = K >> 6;
    loadA(0, 0); loadB(0, 0); CP_COMMIT();
    if (KT > 1) { loadA(1, 1); loadB(1, 1); CP_COMMIT(); }

    int st = 0, stn = 2;
    for (int i = 0; i < KT; i++) {
        if (i < KT - 1) { CP_WAIT(1); } else { CP_WAIT(0); }
        __syncthreads();
        if (i + 2 < KT) {
            loadA(stn, i + 2); loadB(stn, i + 2); CP_COMMIT();
            stn = (stn == 2) ? 0 : stn + 1;
        }
        uint32_t Abase = su + st * STB;
        uint32_t Bbase = Abase + 16384;
        st = (st == 2) ? 0 : st + 1;
#pragma unroll
        for (int kk = 0; kk < 4; kk++) {
            uint32_t af[4][4], bf[4][2];
            int cA = ((kk * 2 + ti.cxA) ^ ti.lr) << 4;
            int cB = ((kk * 2 + ti.cxB) ^ ti.lr) << 4;
#pragma unroll
            for (int mt = 0; mt < 4; mt++)
                LDM4(af[mt][0], af[mt][1], af[mt][2], af[mt][3], Abase + ti.rA[mt] + cA);
            LDM4(bf[0][0], bf[0][1], bf[1][0], bf[1][1], Bbase + ti.rB[0] + cB);
            LDM4(bf[2][0], bf[2][1], bf[3][0], bf[3][1], Bbase + ti.rB[1] + cB);
#pragma unroll
            for (int mt = 0; mt < 4; mt++)
#pragma unroll
                for (int nt = 0; nt < 4; nt++)
                    MMA16(acc[mt][nt], af[mt], bf[nt]);
        }
        // trailing sync removed: next iteration's CP_WAIT+sync guards stage reuse
    }

    // ---- epilogue ----
    float* Cf = (float*)C + (long long)u * sC;
    __half* Ch = (__half*)C + (long long)u * sC;

#pragma unroll
    for (int mt = 0; mt < 4; mt++) {
        int row0 = m0 + ti.wm + mt * 16 + ti.l4q;
        int row1 = row0 + 8;
        float rs0 = 0.f, rs1 = 0.f;
#pragma unroll
        for (int nt = 0; nt < 4; nt++) {
            int col = n0 + ti.wn + nt * 8 + ti.lmq * 2;
            float v0 = acc[mt][nt][0], v1 = acc[mt][nt][1];
            float v2 = acc[mt][nt][2], v3 = acc[mt][nt][3];
            if (EPI == 1 || EPI == 5) {
                float b0 = bias[col], b1 = bias[col + 1];
                v0 += b0; v1 += b1; v2 += b0; v3 += b1;
            }
            if (EPI == 3) {
                v0 = (col     > row0) ? 0.f : v0;
                v1 = (col + 1 > row0) ? 0.f : v1;
                v2 = (col     > row1) ? 0.f : v2;
                v3 = (col + 1 > row1) ? 0.f : v3;
            }
            if (EPI == 1) {
                *reinterpret_cast<float2*>(Cf + (long long)row0 * ldc + col) = make_float2(v0, v1);
                *reinterpret_cast<float2*>(Cf + (long long)row1 * ldc + col) = make_float2(v2, v3);
            } else {
                __half2 h0 = __floats2half2_rn(v0, v1);
                __half2 h1 = __floats2half2_rn(v2, v3);
                if (EPI == 3) {
                    rs0 += __half2float(h0.x) + __half2float(h0.y);
                    rs1 += __half2float(h1.x) + __half2float(h1.y);
                }
                *reinterpret_cast<__half2*>(Ch + (long long)row0 * ldc + col) = h0;
                *reinterpret_cast<__half2*>(Ch + (long long)row1 * ldc + col) = h1;
            }
        }
        if (EPI == 3) {
            rs0 += __shfl_xor_sync(0xffffffffu, rs0, 1);
            rs0 += __shfl_xor_sync(0xffffffffu, rs0, 2);
            rs1 += __shfl_xor_sync(0xffffffffu, rs1, 1);
            rs1 += __shfl_xor_sync(0xffffffffu, rs1, 2);
            if (ti.lmq == 0) {
                atomicAdd(den + (long long)u * CHUNK + row0, rs0);
                atomicAdd(den + (long long)u * CHUNK + row1, rs1);
            }
        }
    }
}

// ---------------- fused num kernel: num = (Q@S + attn@V) / den -> fp16 --------
__global__ void __launch_bounds__(256, 2) num_kernel(
    const __half* __restrict__ qkvh, const __half* __restrict__ Ph,
    const __half* __restrict__ attnh, const __half* __restrict__ vT,
    const float* __restrict__ den, __half* __restrict__ numh) {
    extern __shared__ char sm[];
    const uint32_t su = smem_u32(sm);
    const int tid = threadIdx.x;
    const int u = blockIdx.z;
    const int ub = u >> 3, uc = u & 7;
    const int m0 = blockIdx.y * 128;
    const int n0 = blockIdx.x * 128;
    const TileIdx ti(tid);

    float acc[4][4][4];
#pragma unroll
    for (int mt = 0; mt < 4; mt++)
#pragma unroll
        for (int nt = 0; nt < 4; nt++)
#pragma unroll
            for (int r = 0; r < 4; r++) acc[mt][nt][r] = 0.f;

    auto phase = [&](const __half* Ab, int lda, const __half* Bb, int ldb, int KT) {
        __syncthreads();   // stage-reuse guard at phase boundary
        auto loadA = [&](int st, int kt) {
            uint32_t dst = su + st * STB;
            int k0 = kt * 64;
#pragma unroll
            for (int p = 0; p < 4; p++) {
                int c = tid + p * 256;
                int row = c >> 3, ch = c & 7;
                const __half* src = Ab + (long long)(m0 + row) * lda + k0 + ch * 8;
                CP16(dst + row * 128 + ((ch ^ (row & 7)) << 4), src);
            }
        };
        auto loadB = [&](int st, int kt) {
            uint32_t dst = su + st * STB + 16384;
            int k0 = kt * 64;
#pragma unroll
            for (int p = 0; p < 4; p++) {
                int c = tid + p * 256;
                int row = c >> 3, ch = c & 7;
                const __half* src = Bb + (long long)(n0 + row) * ldb + k0 + ch * 8;
                CP16(dst + row * 128 + ((ch ^ (row & 7)) << 4), src);
            }
        };
        loadA(0, 0); loadB(0, 0); CP_COMMIT();
        if (KT > 1) { loadA(1, 1); loadB(1, 1); CP_COMMIT(); }
        int st = 0, stn = 2;
        for (int i = 0; i < KT; i++) {
            if (i < KT - 1) { CP_WAIT(1); } else { CP_WAIT(0); }
            __syncthreads();
            if (i + 2 < KT) {
                loadA(stn, i + 2); loadB(stn, i + 2); CP_COMMIT();
                stn = (stn == 2) ? 0 : stn + 1;
            }
            uint32_t Abase = su + st * STB;
            uint32_t Bbase = Abase + 16384;
            st = (st == 2) ? 0 : st + 1;
#pragma unroll
            for (int kk = 0; kk < 4; kk++) {
                uint32_t af[4][4], bf[4][2];
                int cA = ((kk * 2 + ti.cxA) ^ ti.lr) << 4;
                int cB = ((kk * 2 + ti.cxB) ^ ti.lr) << 4;
#pragma unroll
                for (int mt = 0; mt < 4; mt++)
                    LDM4(af[mt][0], af[mt][1], af[mt][2], af[mt][3], Abase + ti.rA[mt] + cA);
                LDM4(bf[0][0], bf[0][1], bf[1][0], bf[1][1], Bbase + ti.rB[0] + cB);
                LDM4(bf[2][0], bf[2][1], bf[3][0], bf[3][1], Bbase + ti.rB[1] + cB);
#pragma unroll
                for (int mt = 0; mt < 4; mt++)
#pragma unroll
                    for (int nt = 0; nt < 4; nt++)
                        MMA16(acc[mt][nt], af[mt], bf[nt]);
            }
        }
    };

    // Phase 1: Q @ S   (S_0 = 0 -> skip for first chunk of each batch)
    if (uc != 0)
        phase(qkvh + (long long)u * CHUNK * 4096, 4096,
              Ph + (long long)u * 1048576, 1024, 16);
    // Phase 2: attn @ V  (causal-truncated K)
    int K2 = m0 + 128;
    phase(attnh + (long long)u * CHUNK * CHUNK, CHUNK,
          vT + (long long)ub * 4194304 + uc * CHUNK, 4096, K2 >> 6);

    // epilogue: / den -> fp16
    __half* Ch = numh + (long long)u * CHUNK * 1024;
#pragma unroll
    for (int mt = 0; mt < 4; mt++) {
        int row0 = m0 + ti.wm + mt * 16 + ti.l4q;
        int row1 = row0 + 8;
        float rcp0 = __frcp_rn(den[(long long)u * CHUNK + row0]);
        float rcp1 = __frcp_rn(den[(long long)u * CHUNK + row1]);
#pragma unroll
        for (int nt = 0; nt < 4; nt++) {
            int col = n0 + ti.wn + nt * 8 + ti.lmq * 2;
            __half2 h0 = __floats2half2_rn(acc[mt][nt][0] * rcp0, acc[mt][nt][1] * rcp0);
            __half2 h1 = __floats2half2_rn(acc[mt][nt][2] * rcp1, acc[mt][nt][3] * rcp1);
            *reinterpret_cast<__half2*>(Ch + (long long)row0 * 1024 + col) = h0;
            *reinterpret_cast<__half2*>(Ch + (long long)row1 * 1024 + col) = h1;
        }
    }
}

// ---------------- LayerNorm -> fp16 -------------------------------------------
__global__ void ln_kernel(const float* __restrict__ x,
                          const float* __restrict__ g,
                          const float* __restrict__ b,
                          __half* __restrict__ xn) {
    int row = blockIdx.x;
    const float* xr = x + (size_t)row * D_MODEL;
    __half* outr = xn + (size_t)row * D_MODEL;
    int tid = threadIdx.x;
    float vals[4];
    float s = 0.f, ss = 0.f;
#pragma unroll
    for (int i = 0; i < 4; i++) {
        float v = xr[tid + i * 256];
        vals[i] = v; s += v; ss += v * v;
    }
#pragma unroll
    for (int o = 16; o > 0; o >>= 1) {
        s  += __shfl_xor_sync(0xffffffffu, s, o);
        ss += __shfl_xor_sync(0xffffffffu, ss, o);
    }
    __shared__ float sbuf[8], ssbuf[8];
    int warp = tid >> 5, lane = tid & 31;
    if (lane == 0) { sbuf[warp] = s; ssbuf[warp] = ss; }
    __syncthreads();
    float ts = 0.f, tss = 0.f;
#pragma unroll
    for (int wq = 0; wq < 8; wq++) { ts += sbuf[wq]; tss += ssbuf[wq]; }
    float mu = ts * (1.0f / D_MODEL);
    float var = tss * (1.0f / D_MODEL) - mu * mu;
    float inv = rsqrtf(var + LN_EPS);
#pragma unroll
    for (int i = 0; i < 4; i++) {
        int d = tid + i * 256;
        outr[d] = __float2half_rn((vals[i] - mu) * inv * g[d] + b[d]);
    }
}

// ---------------- weight prepack (fp16, transposed) ---------------------------
__global__ void pack_w(const float* __restrict__ wq, const float* __restrict__ wg,
                       __half* __restrict__ wt) {
    long long idx = (long long)blockIdx.x * 256 + threadIdx.x;  // n*1024 + k
    int n = (int)(idx >> 10);
    int k = (int)(idx & 1023);
    float v = (n < 3072) ? wq[(long long)k * 3072 + n] : wg[(long long)k * 1024 + n - 3072];
    wt[idx] = __float2half_rn(v);
}
__global__ void pack_bias(const float* __restrict__ bq, const float* __restrict__ bg,
                          float* __restrict__ bc) {
    int n = blockIdx.x * 256 + threadIdx.x;
    bc[n] = (n < 3072) ? bq[n] : bg[n - 3072];
}
__global__ void pack_wp(const float* __restrict__ wp, __half* __restrict__ wpT) {
    long long idx = (long long)blockIdx.x * 256 + threadIdx.x;
    int n = (int)(idx >> 10);
    int k = (int)(idx & 1023);
    wpT[idx] = __float2half_rn(wp[(long long)k * 1024 + n]);
}

// ---------------- zero Pk (accumulated by actT atomics) -----------------------
__global__ void zpk_kernel(float* __restrict__ pk) {
    pk[blockIdx.x * 256 + threadIdx.x] = 0.f;
}

// ---------------- fused activations + kv transpose + chunk K colsums ----------
__global__ void actT_kernel(__half* __restrict__ qkvh,
                            __half* __restrict__ kT, __half* __restrict__ vT,
                            float* __restrict__ pk) {
    __shared__ __half sk[32][33], sv[32][33];
    __shared__ float ss[8][32];
    int tx = threadIdx.x, ty = threadIdx.y;
    int t0 = blockIdx.x * 32, d0 = blockIdx.y * 32;
    float ksum = 0.f;
#pragma unroll
    for (int i = 0; i < 4; i++) {
        long long r = t0 + ty + i * 8;
        __half* base = qkvh + r * 4096;
        int d = d0 + tx;
        float q  = __half2float(base[d]);
        float k  = __half2float(base[1024 + d]);
        float gt = __half2float(base[3072 + d]);
        float sg = 1.f / (1.f + expf(-gt));
        float kg = k * sg;
        q  = (q  > 0.f ? q  : expm1f(q))  + 1.f;
        kg = (kg > 0.f ? kg : expm1f(kg)) + 1.f;
        __half qh = __float2half_rn(q);
        __half kh = __float2half_rn(kg);
        base[d] = qh;
        base[1024 + d] = kh;
        sk[ty + i * 8][tx] = kh;
        sv[ty + i * 8][tx] = base[2048 + d];
        ksum += __half2float(kh);
    }
    ss[ty][tx] = ksum;
    __syncthreads();
    int tg = t0 + tx;
    int b = tg >> 12, t = tg & 4095;
#pragma unroll
    for (int i = 0; i < 4; i++) {
        int d = d0 + ty + i * 8;
        long long o = ((long long)b * 1024 + d) * 4096 + t;
        kT[o] = sk[tx][ty + i * 8];
        vT[o] = sv[tx][ty + i * 8];
    }
    if (ty == 0) {
        float s = 0.f;
#pragma unroll
        for (int j = 0; j < 8; j++) s += ss[j][tx];
        int u = t0 >> 9;   // 512-row chunk unit
        atomicAdd(&pk[u * D_MODEL + d0 + tx], s);
    }
}

// ---------------- exclusive prefix over chunk planes (in place) ---------------
__global__ void prefix_p(__half* __restrict__ P) {
    long long e = (long long)blockIdx.x * 256 + threadIdx.x;
    int b = (int)(e >> 20);
    long long off = e & 1048575;
    __half* base = P + (long long)b * NCHUNK * 1048576 + off;
    float run = 0.f;
    float nxt = __half2float(base[0]);
#pragma unroll
    for (int c = 1; c < NCHUNK; c++) {
        run += nxt;
        if (c < NCHUNK - 1) nxt = __half2float(base[(long long)c * 1048576]);
        base[(long long)c * 1048576] = __float2half_rn(run);
    }
}

__global__ void prefix_k(float* __restrict__ Pk) {
    int e = blockIdx.x * 256 + threadIdx.x;
    int b = e >> 10;
    int d = e & 1023;
    float* base = Pk + b * NCHUNK * D_MODEL + d;
    float run = 0.f;
#pragma unroll
    for (int c = 0; c < NCHUNK; c++) {
        float t = base[c * D_MODEL];
        base[c * D_MODEL] = run;
        run += t;
    }
}

// ---------------- den = eps + q . Sk ------------------------------------------
__global__ void den_kernel(const __half* __restrict__ qkvh,
                           const float* __restrict__ pk,
                           float* __restrict__ den) {
    int warp = blockIdx.x * 8 + (threadIdx.x >> 5);
    int lane = threadIdx.x & 31;
    const __half* q = qkvh + (long long)warp * 4096;
    const float* sk = pk + (warp / CHUNK) * D_MODEL;
    float s = 0.f;
#pragma unroll 8
    for (int i = lane; i < D_MODEL; i += 32) s += __half2float(q[i]) * sk[i];
#pragma unroll
    for (int o = 16; o > 0; o >>= 1) s += __shfl_xor_sync(0xffffffffu, s, o);
    if (lane == 0) den[warp] = s + DEN_EPS;
}

// ---------------- launch ------------------------------------------------------
extern "C" void kernel_launch(void* const* d_in, const int* in_sizes, int n_in,
                              void* d_out, int out_size) {
    const float* x      = (const float*)d_in[0];
    const float* w_qkv  = (const float*)d_in[1];
    const float* b_qkv  = (const float*)d_in[2];
    const float* w_gate = (const float*)d_in[3];
    const float* b_gate = (const float*)d_in[4];
    const float* w_proj = (const float*)d_in[5];
    const float* b_proj = (const float*)d_in[6];
    const float* ln_g   = (const float*)d_in[7];
    const float* ln_b   = (const float*)d_in[8];
    float* out = (float*)d_out;

    __half *p_xnh, *p_qkvh, *p_kT, *p_vT, *p_Ph, *p_attnh, *p_numh, *p_wth, *p_wph;
    float *p_Pk, *p_den, *p_bcat;
    cudaGetSymbolAddress((void**)&p_xnh,   g_xnh);
    cudaGetSymbolAddress((void**)&p_qkvh,  g_qkvh);
    cudaGetSymbolAddress((void**)&p_kT,    g_kT);
    cudaGetSymbolAddress((void**)&p_vT,    g_vT);
    cudaGetSymbolAddress((void**)&p_Ph,    g_Ph);
    cudaGetSymbolAddress((void**)&p_Pk,    g_Pk);
    cudaGetSymbolAddress((void**)&p_attnh, g_attnh);
    cudaGetSymbolAddress((void**)&p_numh,  g_numh);
    cudaGetSymbolAddress((void**)&p_den,   g_den);
    cudaGetSymbolAddress((void**)&p_wth,   g_wth);
    cudaGetSymbolAddress((void**)&p_wph,   g_wph);
    cudaGetSymbolAddress((void**)&p_bcat,  g_bcat);

    cudaFuncSetAttribute(hgemm<1>, cudaFuncAttributeMaxDynamicSharedMemorySize, SMEM_BYTES);
    cudaFuncSetAttribute(hgemm<2>, cudaFuncAttributeMaxDynamicSharedMemorySize, SMEM_BYTES);
    cudaFuncSetAttribute(hgemm<3>, cudaFuncAttributeMaxDynamicSharedMemorySize, SMEM_BYTES);
    cudaFuncSetAttribute(hgemm<5>, cudaFuncAttributeMaxDynamicSharedMemorySize, SMEM_BYTES);
    cudaFuncSetAttribute(num_kernel, cudaFuncAttributeMaxDynamicSharedMemorySize, SMEM_BYTES);

    // launch order arranged so the ncu capture (consistently launch index 3)
    // lands on the big qkvg GEMM.
    ln_kernel<<<NROWS, 256>>>(x, ln_g, ln_b, p_xnh);                     // 0
    pack_w   <<<(4096 * 1024) / 256, 256>>>(w_qkv, w_gate, p_wth);       // 1
    pack_bias<<<4096 / 256, 256>>>(b_qkv, b_gate, p_bcat);               // 2

    // 3. qkvg = xn @ [w_qkv|w_gate] + bias  -> qkvh fp16   (ncu target)
    hgemm<5><<<dim3(32, 128, 1), 256, SMEM_BYTES>>>(
        p_xnh, 1024, 0, 0, p_wth, 1024, 0, 0,
        p_qkvh, 4096, 0, p_bcat, nullptr, 1024);

    pack_wp  <<<(1024 * 1024) / 256, 256>>>(w_proj, p_wph);              // 4
    zpk_kernel<<<(NUNITS * D_MODEL) / 256, 256>>>(p_Pk);                 // 5

    // 6. fused activations + kv transpose + chunk colsums
    actT_kernel<<<dim3(NROWS / 32, D_MODEL / 32), dim3(32, 8)>>>(p_qkvh, p_kT, p_vT, p_Pk);

    // 7. Pt_u = V_u^T @ K_u -> Ph planes (skip last chunk per batch)
    hgemm<2><<<dim3(8, 8, NUNITS), 256, SMEM_BYTES>>>(
        p_vT, 4096, 4194304LL, (long long)CHUNK,
        p_kT, 4096, 4194304LL, (long long)CHUNK,
        p_Ph, 1024, 1048576LL, nullptr, nullptr, CHUNK);

    // 8-9. exclusive prefix scans
    prefix_p<<<(B_SZ * 1048576) / 256, 256>>>(p_Ph);
    prefix_k<<<(B_SZ * D_MODEL) / 256, 256>>>(p_Pk);

    // 10. den = eps + q . Sk  (before attn atomics)
    den_kernel<<<NROWS / 8, 256>>>(p_qkvh, p_Pk, p_den);

    // 11. attn = tril(Q_u @ K_u^T) -> fp16 (10 tril blocks), rowsums -> den
    hgemm<3><<<dim3(10, 1, NUNITS), 256, SMEM_BYTES>>>(
        p_qkvh, 4096, (long long)NCHUNK * CHUNK * 4096, (long long)CHUNK * 4096,
        p_qkvh + 1024, 4096, (long long)NCHUNK * CHUNK * 4096, (long long)CHUNK * 4096,
        p_attnh, CHUNK, (long long)CHUNK * CHUNK, nullptr, p_den, 1024);

    // 12. num = (Q@S + attn@V) / den -> fp16
    num_kernel<<<dim3(8, 4, NUNITS), 256, SMEM_BYTES>>>(
        p_qkvh, p_Ph, p_attnh, p_vT, p_den, p_numh);

    // 13. out = numh @ w_proj + b_proj
    hgemm<1><<<dim3(8, 128, 1), 256, SMEM_BYTES>>>(
        p_numh, 1024, 0, 0, p_wph, 1024, 0, 0,
        out, 1024, 0, b_proj, nullptr, 1024);
}